// round 3
// baseline (speedup 1.0000x reference)
#include <cuda_runtime.h>
#include <cuda_bf16.h>
#include <cstdint>

#define BATCH 4096
#define ACT   2048
#define DICT  32768
#define K_TOP 64
#define EPS   8e-4f
#define CAND_CAP 256

// ---------------- device scratch (static, no allocations) ----------------
__device__ __nv_bfloat16 g_Ahi[(size_t)BATCH * ACT];
__device__ __nv_bfloat16 g_Alo[(size_t)BATCH * ACT];
__device__ __nv_bfloat16 g_Bhi[(size_t)DICT * ACT];
__device__ __nv_bfloat16 g_Blo[(size_t)DICT * ACT];
__device__ float         g_WdecT[(size_t)DICT * ACT];   // [DICT][ACT]
__device__ float         g_vals[BATCH * K_TOP];
__device__ int           g_idxs[BATCH * K_TOP];

// ---------------- prep: split fp32 -> bf16 hi/lo ----------------
__global__ void prep_a_kernel(const float* __restrict__ x,
                              const float* __restrict__ b_dec) {
    size_t i = (size_t)blockIdx.x * blockDim.x + threadIdx.x;
    float a = x[i] - __ldg(&b_dec[i & (ACT - 1)]);
    __nv_bfloat16 h = __float2bfloat16(a);
    float lo = a - __bfloat162float(h);
    g_Ahi[i] = h;
    g_Alo[i] = __float2bfloat16(lo);
}

__global__ void prep_b_kernel(const float* __restrict__ W) {
    size_t i = (size_t)blockIdx.x * blockDim.x + threadIdx.x;
    float a = W[i];
    __nv_bfloat16 h = __float2bfloat16(a);
    g_Bhi[i] = h;
    g_Blo[i] = __float2bfloat16(a - __bfloat162float(h));
}

// ---------------- transpose W_dec [ACT][DICT] -> g_WdecT [DICT][ACT] -----
__global__ void transpose_kernel(const float* __restrict__ W) {
    __shared__ float tile[32][33];
    int bx = blockIdx.x * 32;   // dict dim
    int by = blockIdx.y * 32;   // act dim
    int tx = threadIdx.x, ty = threadIdx.y;  // 32 x 8
#pragma unroll
    for (int j = 0; j < 32; j += 8)
        tile[ty + j][tx] = W[(size_t)(by + ty + j) * DICT + bx + tx];
    __syncthreads();
#pragma unroll
    for (int j = 0; j < 32; j += 8)
        g_WdecT[(size_t)(bx + ty + j) * ACT + by + tx] = tile[tx][ty + j];
}

// ---------------- encode GEMM: z = relu((x-b_dec) @ W_enc^T + b_enc) -----
// bf16 split precision: C = Ahi*Bhi + Ahi*Blo + Alo*Bhi (fp32 accumulate)
#define BM 128
#define BN 128
#define BK 32
#define SSTR 40            // bf16 elements per smem row (BK + 8 pad)
#define STAGE_ELEMS (128 * SSTR)   // 5120 per matrix per stage

__device__ __forceinline__ void cp16(unsigned saddr, const void* g) {
    asm volatile("cp.async.cg.shared.global [%0], [%1], 16;\n" ::"r"(saddr), "l"(g));
}

__device__ __forceinline__ void mma_bf16(float* c, const uint32_t* a,
                                         const uint32_t* b) {
    asm volatile(
        "mma.sync.aligned.m16n8k16.row.col.f32.bf16.bf16.f32 "
        "{%0,%1,%2,%3},{%4,%5,%6,%7},{%8,%9},{%0,%1,%2,%3};\n"
        : "+f"(c[0]), "+f"(c[1]), "+f"(c[2]), "+f"(c[3])
        : "r"(a[0]), "r"(a[1]), "r"(a[2]), "r"(a[3]), "r"(b[0]), "r"(b[1]));
}

__global__ void __launch_bounds__(256)
encode_gemm_kernel(const float* __restrict__ b_enc, float* __restrict__ z) {
    extern __shared__ __align__(16) __nv_bfloat16 sm[];
    __nv_bfloat16* sAh = sm;
    __nv_bfloat16* sAl = sm + 2 * STAGE_ELEMS;
    __nv_bfloat16* sBh = sm + 4 * STAGE_ELEMS;
    __nv_bfloat16* sBl = sm + 6 * STAGE_ELEMS;

    const int tid = threadIdx.x;
    const int bx = blockIdx.x * BN;   // dict offset
    const int by = blockIdx.y * BM;   // batch offset
    const int warp = tid >> 5, lane = tid & 31;
    const int wm = (warp & 3) * 32;   // warp m offset in tile
    const int wn = (warp >> 2) * 64;  // warp n offset in tile
    const int g = lane >> 2, tig = lane & 3;

    const unsigned uAh = (unsigned)__cvta_generic_to_shared(sAh);
    const unsigned uAl = (unsigned)__cvta_generic_to_shared(sAl);
    const unsigned uBh = (unsigned)__cvta_generic_to_shared(sBh);
    const unsigned uBl = (unsigned)__cvta_generic_to_shared(sBl);

    float acc[2][8][4];
#pragma unroll
    for (int mi = 0; mi < 2; mi++)
#pragma unroll
        for (int ni = 0; ni < 8; ni++)
#pragma unroll
            for (int q = 0; q < 4; q++) acc[mi][ni][q] = 0.f;

    const int KT = ACT / BK;   // 64

#define LOAD_STAGE(stage, kt)                                                   \
    {                                                                           \
        const int koff = (kt) * BK;                                             \
        _Pragma("unroll")                                                       \
        for (int r = 0; r < 2; r++) {                                           \
            int id = tid + r * 256;                                             \
            int row = id >> 2;                                                  \
            int ch = (id & 3) * 8;                                              \
            unsigned sb = (unsigned)(((stage) * STAGE_ELEMS + row * SSTR + ch) * 2); \
            size_t ga = (size_t)(by + row) * ACT + koff + ch;                   \
            size_t gb = (size_t)(bx + row) * ACT + koff + ch;                   \
            cp16(uAh + sb, &g_Ahi[ga]);                                         \
            cp16(uAl + sb, &g_Alo[ga]);                                         \
            cp16(uBh + sb, &g_Bhi[gb]);                                         \
            cp16(uBl + sb, &g_Blo[gb]);                                         \
        }                                                                       \
    }

    LOAD_STAGE(0, 0);
    asm volatile("cp.async.commit_group;\n");

    for (int kt = 0; kt < KT; kt++) {
        const int cur = kt & 1;
        if (kt + 1 < KT) {
            LOAD_STAGE((kt + 1) & 1, kt + 1);
            asm volatile("cp.async.commit_group;\n");
            asm volatile("cp.async.wait_group 1;\n");
        } else {
            asm volatile("cp.async.wait_group 0;\n");
        }
        __syncthreads();

        const int so = cur * STAGE_ELEMS;
#pragma unroll
        for (int ks = 0; ks < 2; ks++) {
            const int kcol = ks * 16 + tig * 2;
            uint32_t ah[2][4], al[2][4];
#pragma unroll
            for (int mi = 0; mi < 2; mi++) {
                const __nv_bfloat16* pa = &sAh[so + (wm + mi * 16 + g) * SSTR + kcol];
                const __nv_bfloat16* pl = &sAl[so + (wm + mi * 16 + g) * SSTR + kcol];
                ah[mi][0] = *(const uint32_t*)pa;
                ah[mi][1] = *(const uint32_t*)(pa + 8 * SSTR);
                ah[mi][2] = *(const uint32_t*)(pa + 8);
                ah[mi][3] = *(const uint32_t*)(pa + 8 * SSTR + 8);
                al[mi][0] = *(const uint32_t*)pl;
                al[mi][1] = *(const uint32_t*)(pl + 8 * SSTR);
                al[mi][2] = *(const uint32_t*)(pl + 8);
                al[mi][3] = *(const uint32_t*)(pl + 8 * SSTR + 8);
            }
#pragma unroll
            for (int ni = 0; ni < 8; ni++) {
                const __nv_bfloat16* pb = &sBh[so + (wn + ni * 8 + g) * SSTR + kcol];
                const __nv_bfloat16* ql = &sBl[so + (wn + ni * 8 + g) * SSTR + kcol];
                uint32_t bh[2] = {*(const uint32_t*)pb, *(const uint32_t*)(pb + 8)};
                uint32_t bl[2] = {*(const uint32_t*)ql, *(const uint32_t*)(ql + 8)};
#pragma unroll
                for (int mi = 0; mi < 2; mi++) {
                    mma_bf16(acc[mi][ni], ah[mi], bh);
                    mma_bf16(acc[mi][ni], ah[mi], bl);
                    mma_bf16(acc[mi][ni], al[mi], bh);
                }
            }
        }
        __syncthreads();
    }

    // epilogue: +b_enc, relu, write straight into z region of d_out
#pragma unroll
    for (int mi = 0; mi < 2; mi++) {
        int r = by + wm + mi * 16 + g;
#pragma unroll
        for (int ni = 0; ni < 8; ni++) {
            int c = bx + wn + ni * 8 + tig * 2;
            float be0 = __ldg(&b_enc[c]);
            float be1 = __ldg(&b_enc[c + 1]);
            float v0 = fmaxf(acc[mi][ni][0] + be0, 0.f);
            float v1 = fmaxf(acc[mi][ni][1] + be1, 0.f);
            float v2 = fmaxf(acc[mi][ni][2] + be0, 0.f);
            float v3 = fmaxf(acc[mi][ni][3] + be1, 0.f);
            *(float2*)&z[(size_t)r * DICT + c] = make_float2(v0, v1);
            *(float2*)&z[(size_t)(r + 8) * DICT + c] = make_float2(v2, v3);
        }
    }
}

// ---------------- per-row top-K: radix select + fp64-exact boundary refine
__global__ void __launch_bounds__(512) topk_kernel(
    const float* __restrict__ x, const float* __restrict__ W_enc,
    const float* __restrict__ b_enc, const float* __restrict__ b_dec,
    float* __restrict__ z) {
    extern __shared__ __align__(16) unsigned su[];   // DICT uints (128 KB)
    __shared__ float s_x[ACT];                       // (x - b_dec) row, 8 KB
    __shared__ unsigned s_hist[256];
    __shared__ unsigned s_prefix;
    __shared__ int s_remaining;
    __shared__ int s_ncand, s_ncert;
    __shared__ int s_cand_idx[CAND_CAP];
    __shared__ double s_cand_val[CAND_CAP];          // near-exact values
    __shared__ int s_w[16];
    __shared__ int s_o[17];

    const int row = blockIdx.x;
    const int tid = threadIdx.x;
    const int lane = tid & 31, wid = tid >> 5;
    float* zr = z + (size_t)row * DICT;

    for (int i = tid; i < DICT; i += 512) {
        float v = zr[i];
        su[i] = __float_as_uint(fmaxf(v, 0.f));   // all >= 0 -> bits monotone
    }
    if (tid == 0) { s_prefix = 0u; s_remaining = K_TOP; s_ncand = 0; s_ncert = 0; }
    __syncthreads();

    // 4-round radix select (MSB->LSB bytes): bits of K-th largest approx val
#pragma unroll
    for (int shift = 24; shift >= 0; shift -= 8) {
        if (tid < 256) s_hist[tid] = 0u;
        __syncthreads();
        unsigned pfx = s_prefix;
        for (int i = tid; i < DICT; i += 512) {
            unsigned u = su[i];
            bool ok = (shift == 24) ? true
                                    : ((u >> (shift + 8)) == (pfx >> (shift + 8)));
            if (ok) atomicAdd(&s_hist[(u >> shift) & 255u], 1u);
        }
        __syncthreads();
        if (tid == 0) {
            int rem = s_remaining;
            unsigned acc = 0;
            int b = 255;
            for (; b > 0; b--) {
                if (acc + s_hist[b] >= (unsigned)rem) break;
                acc += s_hist[b];
            }
            s_prefix = pfx | ((unsigned)b << shift);
            s_remaining = rem - (int)acc;
        }
        __syncthreads();
    }

    const float Tf = __uint_as_float(s_prefix);
    const float hi = Tf + EPS;
    const float lo = Tf - EPS;

    // Pass A: count certain ins (v > hi), collect boundary candidates
    {
        int local_cert = 0;
        for (int i = tid; i < DICT; i += 512) {
            float v = __uint_as_float(su[i]);
            if (v > hi) {
                local_cert++;
            } else if (v >= lo) {
                int p = atomicAdd(&s_ncand, 1);
                if (p < CAND_CAP) s_cand_idx[p] = i;
            }
        }
        atomicAdd(&s_ncert, local_cert);
    }
    __syncthreads();

    const int ncand = min(s_ncand, CAND_CAP);
    const int slots = K_TOP - s_ncert;   // candidates to accept

    if (ncand > 0) {
        // stage (x - b_dec): identical fp32 subtraction as reference
        for (int k = tid; k < ACT; k += 512)
            s_x[k] = x[(size_t)row * ACT + k] - b_dec[k];
        __syncthreads();

        // near-exact pre_act: double-precision lane chains + double tree
        // reduce (error ~1e-13, far below any fp32 reference's rounding)
        for (int c = wid; c < ncand; c += 16) {
            const int m = s_cand_idx[c];
            const float* w = &W_enc[(size_t)m * ACT];
            double acc = 0.0;
            const int k0 = lane * (ACT / 32);
#pragma unroll 8
            for (int k = k0; k < k0 + ACT / 32; k++)
                acc = fma((double)s_x[k], (double)__ldg(&w[k]), acc);
#pragma unroll
            for (int off = 16; off; off >>= 1)
                acc += __shfl_down_sync(0xffffffffu, acc, off);
            if (lane == 0) {
                double v = acc + (double)__ldg(&b_enc[m]);
                s_cand_val[c] = v > 0.0 ? v : 0.0;
            }
        }
        __syncthreads();

        // rank candidates by (exact val desc, index asc); mark winners in su
        if (tid < ncand) {
            const double vi = s_cand_val[tid];
            const int ii = s_cand_idx[tid];
            int r = 0;
            for (int j = 0; j < ncand; j++) {
                double vj = s_cand_val[j];
                if (vj > vi || (vj == vi && s_cand_idx[j] < ii)) r++;
            }
            su[ii] = (r < slots)
                         ? (__float_as_uint((float)vi) | 0x80000000u)
                         : 0u;
        }
        __syncthreads();
    }

    // Pass D: final selection, write z + compact (idx,val) lists
    int base = 0;
    const unsigned lmask = (1u << lane) - 1u;
    for (int start = 0; start < DICT; start += 512) {
        int i = start + tid;
        unsigned u = su[i];
        bool selc = (u & 0x80000000u) != 0u;
        float uv = __uint_as_float(u & 0x7fffffffu);
        bool sel = selc || (uv > hi);
        unsigned b = __ballot_sync(0xffffffffu, sel);
        if (lane == 0) s_w[wid] = __popc(b);
        __syncthreads();
        if (tid == 0) {
            int a = 0;
            for (int w = 0; w < 16; w++) { s_o[w] = a; a += s_w[w]; }
            s_o[16] = a;
        }
        __syncthreads();
        zr[i] = sel ? uv : 0.f;
        if (sel) {
            int slot = base + s_o[wid] + __popc(b & lmask);
            g_idxs[row * K_TOP + slot] = i;
            g_vals[row * K_TOP + slot] = uv;
        }
        base += s_o[16];
        __syncthreads();
    }
}

// ---------------- decode: x_hat = sum_k vals * W_decT[idx] + b_dec --------
__global__ void __launch_bounds__(256)
decode_kernel(const float* __restrict__ b_dec, float* __restrict__ xhat) {
    __shared__ int s_idx[K_TOP];
    __shared__ float s_val[K_TOP];
    const int row = blockIdx.x;
    const int tid = threadIdx.x;
    if (tid < K_TOP) {
        s_idx[tid] = g_idxs[row * K_TOP + tid];
        s_val[tid] = g_vals[row * K_TOP + tid];
    }
    __syncthreads();
    const int d0 = tid * 4;
    const int d1 = 1024 + tid * 4;
    float4 a0 = *(const float4*)&b_dec[d0];
    float4 a1 = *(const float4*)&b_dec[d1];
#pragma unroll 4
    for (int k = 0; k < K_TOP; k++) {
        const float* w = &g_WdecT[(size_t)s_idx[k] * ACT];
        float v = s_val[k];
        float4 w0 = *(const float4*)&w[d0];
        float4 w1 = *(const float4*)&w[d1];
        a0.x += v * w0.x; a0.y += v * w0.y; a0.z += v * w0.z; a0.w += v * w0.w;
        a1.x += v * w1.x; a1.y += v * w1.y; a1.z += v * w1.z; a1.w += v * w1.w;
    }
    *(float4*)&xhat[(size_t)row * ACT + d0] = a0;
    *(float4*)&xhat[(size_t)row * ACT + d1] = a1;
}

// ---------------- launch ----------------
extern "C" void kernel_launch(void* const* d_in, const int* in_sizes, int n_in,
                              void* d_out, int out_size) {
    (void)in_sizes; (void)n_in; (void)out_size;
    const float* x     = (const float*)d_in[0];
    const float* W_enc = (const float*)d_in[1];
    const float* b_enc = (const float*)d_in[2];
    const float* W_dec = (const float*)d_in[3];
    const float* b_dec = (const float*)d_in[4];
    float* xhat = (float*)d_out;
    float* z    = xhat + (size_t)BATCH * ACT;

    prep_a_kernel<<<(BATCH * (size_t)ACT) / 256, 256>>>(x, b_dec);
    prep_b_kernel<<<(DICT * (size_t)ACT) / 256, 256>>>(W_enc);
    transpose_kernel<<<dim3(DICT / 32, ACT / 32), dim3(32, 8)>>>(W_dec);

    const int gemm_smem = 8 * STAGE_ELEMS * (int)sizeof(__nv_bfloat16);  // 81920
    cudaFuncSetAttribute(encode_gemm_kernel,
                         cudaFuncAttributeMaxDynamicSharedMemorySize, gemm_smem);
    encode_gemm_kernel<<<dim3(DICT / BN, BATCH / BM), 256, gemm_smem>>>(b_enc, z);

    cudaFuncSetAttribute(topk_kernel,
                         cudaFuncAttributeMaxDynamicSharedMemorySize, DICT * 4);
    topk_kernel<<<BATCH, 512, DICT * 4>>>(x, W_enc, b_enc, b_dec, z);

    decode_kernel<<<BATCH, 256>>>(b_dec, xhat);
}

// round 5
// speedup vs baseline: 1.7205x; 1.7205x over previous
#include <cuda_runtime.h>
#include <cuda_fp16.h>
#include <cstdint>

#define BATCH 4096
#define ACT   2048
#define DICT  32768
#define K_TOP 64
#define EPS   5e-3f
#define CAND_CAP 256

// ---------------- device scratch (static, no allocations) ----------------
__device__ __half g_Af[(size_t)BATCH * ACT];
__device__ __half g_Bf[(size_t)DICT * ACT];
__device__ float  g_WdecT[(size_t)DICT * ACT];   // [DICT][ACT]
__device__ float  g_vals[BATCH * K_TOP];
__device__ int    g_idxs[BATCH * K_TOP];

// ---------------- prep: fp32 -> fp16 ----------------
__global__ void prep_a_kernel(const float* __restrict__ x,
                              const float* __restrict__ b_dec) {
    size_t i = (size_t)blockIdx.x * blockDim.x + threadIdx.x;
    g_Af[i] = __float2half(x[i] - __ldg(&b_dec[i & (ACT - 1)]));
}

__global__ void prep_b_kernel(const float* __restrict__ W) {
    size_t i = (size_t)blockIdx.x * blockDim.x + threadIdx.x;
    g_Bf[i] = __float2half(W[i]);
}

// ---------------- transpose W_dec [ACT][DICT] -> g_WdecT [DICT][ACT] -----
__global__ void transpose_kernel(const float* __restrict__ W) {
    __shared__ float tile[32][33];
    int bx = blockIdx.x * 32;   // dict dim
    int by = blockIdx.y * 32;   // act dim
    int tx = threadIdx.x, ty = threadIdx.y;  // 32 x 8
#pragma unroll
    for (int j = 0; j < 32; j += 8)
        tile[ty + j][tx] = W[(size_t)(by + ty + j) * DICT + bx + tx];
    __syncthreads();
#pragma unroll
    for (int j = 0; j < 32; j += 8)
        g_WdecT[(size_t)(bx + ty + j) * ACT + by + tx] = tile[tx][ty + j];
}

// ---------------- encode GEMM: z = relu((x-b_dec) @ W_enc^T + b_enc) -----
// single fp16 term, fp32 accumulate; 128x128 tile, BK=64, 3-stage cp.async
#define BM 128
#define BN 128
#define BK 64
#define SSTR 72                       // fp16 elems per smem row (BK + 8 pad)
#define STAGE_ELEMS (128 * SSTR)      // per matrix per stage (9216)
#define NSTAGE 3
#define GEMM_SMEM (NSTAGE * 2 * STAGE_ELEMS * 2)   // 110592 B

__device__ __forceinline__ void cp16(unsigned saddr, const void* g) {
    asm volatile("cp.async.cg.shared.global [%0], [%1], 16;\n" ::"r"(saddr), "l"(g));
}

__device__ __forceinline__ void mma_f16(float* c, const uint32_t* a,
                                        const uint32_t* b) {
    asm volatile(
        "mma.sync.aligned.m16n8k16.row.col.f32.f16.f16.f32 "
        "{%0,%1,%2,%3},{%4,%5,%6,%7},{%8,%9},{%0,%1,%2,%3};\n"
        : "+f"(c[0]), "+f"(c[1]), "+f"(c[2]), "+f"(c[3])
        : "r"(a[0]), "r"(a[1]), "r"(a[2]), "r"(a[3]), "r"(b[0]), "r"(b[1]));
}

__global__ void __launch_bounds__(256)
encode_gemm_kernel(const float* __restrict__ b_enc, float* __restrict__ z) {
    extern __shared__ __align__(16) __half sm[];

    const int tid = threadIdx.x;
    const int bx = blockIdx.x * BN;   // dict offset
    const int by = blockIdx.y * BM;   // batch offset
    const int warp = tid >> 5, lane = tid & 31;
    const int wm = (warp & 3) * 32;   // warp m offset in tile
    const int wn = (warp >> 2) * 64;  // warp n offset in tile
    const int g = lane >> 2, tig = lane & 3;

    const unsigned uS = (unsigned)__cvta_generic_to_shared(sm);

    float acc[2][8][4];
#pragma unroll
    for (int mi = 0; mi < 2; mi++)
#pragma unroll
        for (int ni = 0; ni < 8; ni++)
#pragma unroll
            for (int q = 0; q < 4; q++) acc[mi][ni][q] = 0.f;

    const int KT = ACT / BK;   // 32

    // stage loader: 1024 ids per matrix, 256 threads -> 4 ids each
#define LOAD_STAGE(stage, kt)                                                  \
    {                                                                          \
        const int koff = (kt) * BK;                                            \
        _Pragma("unroll")                                                      \
        for (int r = 0; r < 4; r++) {                                          \
            int id = tid + r * 256;                                            \
            int row = id >> 3;                                                 \
            int ch = (id & 7) * 8;                                             \
            unsigned sa =                                                      \
                (unsigned)(((stage) * 2 * STAGE_ELEMS + row * SSTR + ch) * 2); \
            cp16(uS + sa, &g_Af[(size_t)(by + row) * ACT + koff + ch]);        \
            cp16(uS + sa + STAGE_ELEMS * 2,                                    \
                 &g_Bf[(size_t)(bx + row) * ACT + koff + ch]);                 \
        }                                                                      \
    }

    LOAD_STAGE(0, 0);
    asm volatile("cp.async.commit_group;\n");
    LOAD_STAGE(1, 1);
    asm volatile("cp.async.commit_group;\n");

    for (int kt = 0; kt < KT; kt++) {
        const int cur = kt % 3;
        if (kt + 2 < KT) {
            LOAD_STAGE((kt + 2) % 3, kt + 2);
            asm volatile("cp.async.commit_group;\n");
            asm volatile("cp.async.wait_group 2;\n");
        } else if (kt + 1 < KT) {
            asm volatile("cp.async.wait_group 1;\n");
        } else {
            asm volatile("cp.async.wait_group 0;\n");
        }
        __syncthreads();

        const __half* sA = sm + cur * 2 * STAGE_ELEMS;
        const __half* sB = sA + STAGE_ELEMS;
#pragma unroll
        for (int ks = 0; ks < 4; ks++) {
            const int kcol = ks * 16 + tig * 2;
            uint32_t af[2][4];
#pragma unroll
            for (int mi = 0; mi < 2; mi++) {
                const __half* pa = &sA[(wm + mi * 16 + g) * SSTR + kcol];
                af[mi][0] = *(const uint32_t*)pa;
                af[mi][1] = *(const uint32_t*)(pa + 8 * SSTR);
                af[mi][2] = *(const uint32_t*)(pa + 8);
                af[mi][3] = *(const uint32_t*)(pa + 8 * SSTR + 8);
            }
#pragma unroll
            for (int ni = 0; ni < 8; ni++) {
                const __half* pb = &sB[(wn + ni * 8 + g) * SSTR + kcol];
                uint32_t bf[2] = {*(const uint32_t*)pb, *(const uint32_t*)(pb + 8)};
#pragma unroll
                for (int mi = 0; mi < 2; mi++) mma_f16(acc[mi][ni], af[mi], bf);
            }
        }
        __syncthreads();
    }

    // epilogue: +b_enc, relu, write straight into z region of d_out
#pragma unroll
    for (int mi = 0; mi < 2; mi++) {
        int r = by + wm + mi * 16 + g;
#pragma unroll
        for (int ni = 0; ni < 8; ni++) {
            int c = bx + wn + ni * 8 + tig * 2;
            float be0 = __ldg(&b_enc[c]);
            float be1 = __ldg(&b_enc[c + 1]);
            float v0 = fmaxf(acc[mi][ni][0] + be0, 0.f);
            float v1 = fmaxf(acc[mi][ni][1] + be1, 0.f);
            float v2 = fmaxf(acc[mi][ni][2] + be0, 0.f);
            float v3 = fmaxf(acc[mi][ni][3] + be1, 0.f);
            *(float2*)&z[(size_t)r * DICT + c] = make_float2(v0, v1);
            *(float2*)&z[(size_t)(r + 8) * DICT + c] = make_float2(v2, v3);
        }
    }
}

// ---------------- per-row top-K: radix select + fp64-exact boundary refine
__global__ void __launch_bounds__(512) topk_kernel(
    const float* __restrict__ x, const float* __restrict__ W_enc,
    const float* __restrict__ b_enc, const float* __restrict__ b_dec,
    float* __restrict__ z) {
    extern __shared__ __align__(16) unsigned su[];   // DICT uints (128 KB)
    __shared__ float s_x[ACT];
    __shared__ unsigned s_hist[256];
    __shared__ unsigned s_prefix;
    __shared__ int s_remaining;
    __shared__ int s_ncand, s_ncert;
    __shared__ int s_cand_idx[CAND_CAP];
    __shared__ double s_cand_val[CAND_CAP];
    __shared__ int s_w[16];
    __shared__ int s_o[17];

    const int row = blockIdx.x;
    const int tid = threadIdx.x;
    const int lane = tid & 31, wid = tid >> 5;
    float* zr = z + (size_t)row * DICT;

    for (int i = tid; i < DICT; i += 512) {
        float v = zr[i];
        su[i] = __float_as_uint(fmaxf(v, 0.f));
    }
    if (tid == 0) { s_prefix = 0u; s_remaining = K_TOP; s_ncand = 0; s_ncert = 0; }
    __syncthreads();

#pragma unroll
    for (int shift = 24; shift >= 0; shift -= 8) {
        if (tid < 256) s_hist[tid] = 0u;
        __syncthreads();
        unsigned pfx = s_prefix;
        for (int i = tid; i < DICT; i += 512) {
            unsigned u = su[i];
            bool ok = (shift == 24) ? true
                                    : ((u >> (shift + 8)) == (pfx >> (shift + 8)));
            if (ok) atomicAdd(&s_hist[(u >> shift) & 255u], 1u);
        }
        __syncthreads();
        if (tid == 0) {
            int rem = s_remaining;
            unsigned acc = 0;
            int b = 255;
            for (; b > 0; b--) {
                if (acc + s_hist[b] >= (unsigned)rem) break;
                acc += s_hist[b];
            }
            s_prefix = pfx | ((unsigned)b << shift);
            s_remaining = rem - (int)acc;
        }
        __syncthreads();
    }

    const float Tf = __uint_as_float(s_prefix);
    const float hi = Tf + EPS;
    const float lo = Tf - EPS;

    {
        int local_cert = 0;
        for (int i = tid; i < DICT; i += 512) {
            float v = __uint_as_float(su[i]);
            if (v > hi) {
                local_cert++;
            } else if (v >= lo) {
                int p = atomicAdd(&s_ncand, 1);
                if (p < CAND_CAP) s_cand_idx[p] = i;
            }
        }
        atomicAdd(&s_ncert, local_cert);
    }
    __syncthreads();

    const int ncand = min(s_ncand, CAND_CAP);
    const int slots = K_TOP - s_ncert;

    if (ncand > 0) {
        for (int k = tid; k < ACT; k += 512)
            s_x[k] = x[(size_t)row * ACT + k] - b_dec[k];
        __syncthreads();

        for (int c = wid; c < ncand; c += 16) {
            const int m = s_cand_idx[c];
            const float* w = &W_enc[(size_t)m * ACT];
            double acc = 0.0;
            const int k0 = lane * (ACT / 32);
#pragma unroll 8
            for (int k = k0; k < k0 + ACT / 32; k++)
                acc = fma((double)s_x[k], (double)__ldg(&w[k]), acc);
#pragma unroll
            for (int off = 16; off; off >>= 1)
                acc += __shfl_down_sync(0xffffffffu, acc, off);
            if (lane == 0) {
                double v = acc + (double)__ldg(&b_enc[m]);
                s_cand_val[c] = v > 0.0 ? v : 0.0;
            }
        }
        __syncthreads();

        if (tid < ncand) {
            const double vi = s_cand_val[tid];
            const int ii = s_cand_idx[tid];
            int r = 0;
            for (int j = 0; j < ncand; j++) {
                double vj = s_cand_val[j];
                if (vj > vi || (vj == vi && s_cand_idx[j] < ii)) r++;
            }
            su[ii] = (r < slots) ? (__float_as_uint((float)vi) | 0x80000000u) : 0u;
        }
        __syncthreads();
    }

    int base = 0;
    const unsigned lmask = (1u << lane) - 1u;
    for (int start = 0; start < DICT; start += 512) {
        int i = start + tid;
        unsigned u = su[i];
        bool selc = (u & 0x80000000u) != 0u;
        float uv = __uint_as_float(u & 0x7fffffffu);
        bool sel = selc || (uv > hi);
        unsigned b = __ballot_sync(0xffffffffu, sel);
        if (lane == 0) s_w[wid] = __popc(b);
        __syncthreads();
        if (tid == 0) {
            int a = 0;
            for (int w = 0; w < 16; w++) { s_o[w] = a; a += s_w[w]; }
            s_o[16] = a;
        }
        __syncthreads();
        zr[i] = sel ? uv : 0.f;
        if (sel) {
            int slot = base + s_o[wid] + __popc(b & lmask);
            g_idxs[row * K_TOP + slot] = i;
            g_vals[row * K_TOP + slot] = uv;
        }
        base += s_o[16];
        __syncthreads();
    }
}

// ---------------- decode: x_hat = sum_k vals * W_decT[idx] + b_dec --------
__global__ void __launch_bounds__(256)
decode_kernel(const float* __restrict__ b_dec, float* __restrict__ xhat) {
    __shared__ int s_idx[K_TOP];
    __shared__ float s_val[K_TOP];
    const int row = blockIdx.x;
    const int tid = threadIdx.x;
    if (tid < K_TOP) {
        s_idx[tid] = g_idxs[row * K_TOP + tid];
        s_val[tid] = g_vals[row * K_TOP + tid];
    }
    __syncthreads();
    const int d0 = tid * 4;
    const int d1 = 1024 + tid * 4;
    float4 a0 = *(const float4*)&b_dec[d0];
    float4 a1 = *(const float4*)&b_dec[d1];
#pragma unroll 4
    for (int k = 0; k < K_TOP; k++) {
        const float* w = &g_WdecT[(size_t)s_idx[k] * ACT];
        float v = s_val[k];
        float4 w0 = *(const float4*)&w[d0];
        float4 w1 = *(const float4*)&w[d1];
        a0.x += v * w0.x; a0.y += v * w0.y; a0.z += v * w0.z; a0.w += v * w0.w;
        a1.x += v * w1.x; a1.y += v * w1.y; a1.z += v * w1.z; a1.w += v * w1.w;
    }
    *(float4*)&xhat[(size_t)row * ACT + d0] = a0;
    *(float4*)&xhat[(size_t)row * ACT + d1] = a1;
}

// ---------------- launch ----------------
extern "C" void kernel_launch(void* const* d_in, const int* in_sizes, int n_in,
                              void* d_out, int out_size) {
    (void)in_sizes; (void)n_in; (void)out_size;
    const float* x     = (const float*)d_in[0];
    const float* W_enc = (const float*)d_in[1];
    const float* b_enc = (const float*)d_in[2];
    const float* W_dec = (const float*)d_in[3];
    const float* b_dec = (const float*)d_in[4];
    float* xhat = (float*)d_out;
    float* z    = xhat + (size_t)BATCH * ACT;

    prep_a_kernel<<<(BATCH * (size_t)ACT) / 256, 256>>>(x, b_dec);
    prep_b_kernel<<<(DICT * (size_t)ACT) / 256, 256>>>(W_enc);
    transpose_kernel<<<dim3(DICT / 32, ACT / 32), dim3(32, 8)>>>(W_dec);

    cudaFuncSetAttribute(encode_gemm_kernel,
                         cudaFuncAttributeMaxDynamicSharedMemorySize, GEMM_SMEM);
    encode_gemm_kernel<<<dim3(DICT / BN, BATCH / BM), 256, GEMM_SMEM>>>(b_enc, z);

    cudaFuncSetAttribute(topk_kernel,
                         cudaFuncAttributeMaxDynamicSharedMemorySize, DICT * 4);
    topk_kernel<<<BATCH, 512, DICT * 4>>>(x, W_enc, b_enc, b_dec, z);

    decode_kernel<<<BATCH, 256>>>(b_dec, xhat);
}

// round 6
// speedup vs baseline: 2.1777x; 1.2658x over previous
#include <cuda_runtime.h>
#include <cuda_fp16.h>
#include <cstdint>

#define BATCH 4096
#define ACT   2048
#define DICT  32768
#define K_TOP 64
#define EPS   5e-3f
#define CAND_CAP 256

// ---------------- device scratch (static, no allocations) ----------------
__device__ __half g_Af[(size_t)BATCH * ACT];
__device__ __half g_Bf[(size_t)DICT * ACT];
__device__ __half g_WdecTh[(size_t)DICT * ACT];   // [DICT][ACT] fp16
__device__ float  g_vals[BATCH * K_TOP];
__device__ int    g_idxs[BATCH * K_TOP];

// ---------------- prep: fp32 -> fp16 ----------------
__global__ void prep_a_kernel(const float* __restrict__ x,
                              const float* __restrict__ b_dec) {
    size_t i = (size_t)blockIdx.x * blockDim.x + threadIdx.x;
    g_Af[i] = __float2half(x[i] - __ldg(&b_dec[i & (ACT - 1)]));
}

__global__ void prep_b_kernel(const float* __restrict__ W) {
    size_t i4 = ((size_t)blockIdx.x * blockDim.x + threadIdx.x) * 4;
    float4 v = *(const float4*)&W[i4];
    __half2* o = (__half2*)&g_Bf[i4];
    o[0] = __floats2half2_rn(v.x, v.y);
    o[1] = __floats2half2_rn(v.z, v.w);
}

// ---------------- transpose W_dec [ACT][DICT] -> g_WdecTh [DICT][ACT] ----
__global__ void transpose_kernel(const float* __restrict__ W) {
    __shared__ float tile[32][33];
    int bx = blockIdx.x * 32;   // dict dim
    int by = blockIdx.y * 32;   // act dim
    int tx = threadIdx.x, ty = threadIdx.y;  // 32 x 8
#pragma unroll
    for (int j = 0; j < 32; j += 8)
        tile[ty + j][tx] = W[(size_t)(by + ty + j) * DICT + bx + tx];
    __syncthreads();
#pragma unroll
    for (int j = 0; j < 32; j += 8)
        g_WdecTh[(size_t)(bx + ty + j) * ACT + by + tx] =
            __float2half(tile[tx][ty + j]);
}

// ---------------- encode GEMM: z = relu((x-b_dec) @ W_enc^T + b_enc) -----
// single fp16 term, fp32 accumulate; 128x128 tile, BK=64, 2-stage, 2 CTA/SM
#define BM 128
#define BN 128
#define BK 64
#define SSTR 72                       // fp16 elems per smem row (BK + 8 pad)
#define STAGE_ELEMS (128 * SSTR)      // per matrix per stage (9216)
#define NSTAGE 2
#define GEMM_SMEM (NSTAGE * 2 * STAGE_ELEMS * 2)   // 73728 B -> 2 CTA/SM

__device__ __forceinline__ void cp16(unsigned saddr, const void* g) {
    asm volatile("cp.async.cg.shared.global [%0], [%1], 16;\n" ::"r"(saddr), "l"(g));
}

__device__ __forceinline__ void mma_f16(float* c, const uint32_t* a,
                                        const uint32_t* b) {
    asm volatile(
        "mma.sync.aligned.m16n8k16.row.col.f32.f16.f16.f32 "
        "{%0,%1,%2,%3},{%4,%5,%6,%7},{%8,%9},{%0,%1,%2,%3};\n"
        : "+f"(c[0]), "+f"(c[1]), "+f"(c[2]), "+f"(c[3])
        : "r"(a[0]), "r"(a[1]), "r"(a[2]), "r"(a[3]), "r"(b[0]), "r"(b[1]));
}

__global__ void __launch_bounds__(256, 2)
encode_gemm_kernel(const float* __restrict__ b_enc, float* __restrict__ z) {
    extern __shared__ __align__(16) __half sm[];

    const int tid = threadIdx.x;
    const int by = blockIdx.x * BM;   // batch offset (fast grid dim!)
    const int bx = blockIdx.y * BN;   // dict offset
    const int warp = tid >> 5, lane = tid & 31;
    const int wm = (warp & 3) * 32;
    const int wn = (warp >> 2) * 64;
    const int g = lane >> 2, tig = lane & 3;

    const unsigned uS = (unsigned)__cvta_generic_to_shared(sm);

    float acc[2][8][4];
#pragma unroll
    for (int mi = 0; mi < 2; mi++)
#pragma unroll
        for (int ni = 0; ni < 8; ni++)
#pragma unroll
            for (int q = 0; q < 4; q++) acc[mi][ni][q] = 0.f;

    const int KT = ACT / BK;   // 32

#define LOAD_STAGE(stage, kt)                                                  \
    {                                                                          \
        const int koff = (kt) * BK;                                            \
        _Pragma("unroll")                                                      \
        for (int r = 0; r < 4; r++) {                                          \
            int id = tid + r * 256;                                            \
            int row = id >> 3;                                                 \
            int ch = (id & 7) * 8;                                             \
            unsigned sa =                                                      \
                (unsigned)(((stage) * 2 * STAGE_ELEMS + row * SSTR + ch) * 2); \
            cp16(uS + sa, &g_Af[(size_t)(by + row) * ACT + koff + ch]);        \
            cp16(uS + sa + STAGE_ELEMS * 2,                                    \
                 &g_Bf[(size_t)(bx + row) * ACT + koff + ch]);                 \
        }                                                                      \
    }

    LOAD_STAGE(0, 0);
    asm volatile("cp.async.commit_group;\n");

    for (int kt = 0; kt < KT; kt++) {
        const int cur = kt & 1;
        if (kt + 1 < KT) {
            LOAD_STAGE((kt + 1) & 1, kt + 1);
            asm volatile("cp.async.commit_group;\n");
            asm volatile("cp.async.wait_group 1;\n");
        } else {
            asm volatile("cp.async.wait_group 0;\n");
        }
        __syncthreads();

        const __half* sA = sm + cur * 2 * STAGE_ELEMS;
        const __half* sB = sA + STAGE_ELEMS;
#pragma unroll
        for (int ks = 0; ks < 4; ks++) {
            const int kcol = ks * 16 + tig * 2;
            uint32_t af[2][4];
#pragma unroll
            for (int mi = 0; mi < 2; mi++) {
                const __half* pa = &sA[(wm + mi * 16 + g) * SSTR + kcol];
                af[mi][0] = *(const uint32_t*)pa;
                af[mi][1] = *(const uint32_t*)(pa + 8 * SSTR);
                af[mi][2] = *(const uint32_t*)(pa + 8);
                af[mi][3] = *(const uint32_t*)(pa + 8 * SSTR + 8);
            }
#pragma unroll
            for (int ni = 0; ni < 8; ni++) {
                const __half* pb = &sB[(wn + ni * 8 + g) * SSTR + kcol];
                uint32_t bf[2] = {*(const uint32_t*)pb, *(const uint32_t*)(pb + 8)};
#pragma unroll
                for (int mi = 0; mi < 2; mi++) mma_f16(acc[mi][ni], af[mi], bf);
            }
        }
        __syncthreads();
    }

    // epilogue: +b_enc, relu, write straight into z region of d_out
#pragma unroll
    for (int mi = 0; mi < 2; mi++) {
        int r = by + wm + mi * 16 + g;
#pragma unroll
        for (int ni = 0; ni < 8; ni++) {
            int c = bx + wn + ni * 8 + tig * 2;
            float be0 = __ldg(&b_enc[c]);
            float be1 = __ldg(&b_enc[c + 1]);
            float v0 = fmaxf(acc[mi][ni][0] + be0, 0.f);
            float v1 = fmaxf(acc[mi][ni][1] + be1, 0.f);
            float v2 = fmaxf(acc[mi][ni][2] + be0, 0.f);
            float v3 = fmaxf(acc[mi][ni][3] + be1, 0.f);
            *(float2*)&z[(size_t)r * DICT + c] = make_float2(v0, v1);
            *(float2*)&z[(size_t)(r + 8) * DICT + c] = make_float2(v2, v3);
        }
    }
}

// ---------------- per-row top-K: radix select + fp64-exact boundary refine
__global__ void __launch_bounds__(512) topk_kernel(
    const float* __restrict__ x, const float* __restrict__ W_enc,
    const float* __restrict__ b_enc, const float* __restrict__ b_dec,
    float* __restrict__ z) {
    extern __shared__ __align__(16) unsigned su[];   // DICT uints (128 KB)
    __shared__ float s_x[ACT];
    __shared__ unsigned s_hist[256];
    __shared__ unsigned s_gsum[8];
    __shared__ unsigned s_prefix;
    __shared__ int s_remaining;
    __shared__ int s_ncand, s_ncert;
    __shared__ int s_cand_idx[CAND_CAP];
    __shared__ double s_cand_val[CAND_CAP];
    __shared__ int s_cntf[1024];   // (chunk c, warp w) flattened: j = c*16+w
    __shared__ int s_excl[1024];
    __shared__ int s_wtot[16], s_wbase[16];

    const unsigned FULL = 0xffffffffu;
    const int row = blockIdx.x;
    const int tid = threadIdx.x;
    const int lane = tid & 31, wid = tid >> 5;
    float* zr = z + (size_t)row * DICT;

    for (int i = tid; i < DICT; i += 512) {
        float v = zr[i];
        su[i] = __float_as_uint(fmaxf(v, 0.f));
    }
    if (tid == 0) { s_prefix = 0u; s_remaining = K_TOP; s_ncand = 0; s_ncert = 0; }
    __syncthreads();

    // 4-round radix select (MSB->LSB bytes)
#pragma unroll
    for (int shift = 24; shift >= 0; shift -= 8) {
        if (tid < 256) s_hist[tid] = 0u;
        __syncthreads();
        unsigned pfx = s_prefix;
        for (int i = tid; i < DICT; i += 512) {
            unsigned u = su[i];
            bool ok = (shift == 24) ? true
                                    : ((u >> (shift + 8)) == (pfx >> (shift + 8)));
            if (ok) atomicAdd(&s_hist[(u >> shift) & 255u], 1u);
        }
        __syncthreads();
        if (tid < 256) {   // warp-reduced group sums (8 groups of 32 buckets)
            unsigned v = s_hist[tid];
#pragma unroll
            for (int off = 16; off; off >>= 1)
                v += __shfl_down_sync(FULL, v, off);
            if (lane == 0) s_gsum[tid >> 5] = v;
        }
        __syncthreads();
        if (tid == 0) {
            int rem = s_remaining;
            unsigned acc = 0;
            int grp = 7;
            for (; grp > 0; grp--) {
                if (acc + s_gsum[grp] >= (unsigned)rem) break;
                acc += s_gsum[grp];
            }
            int b = grp * 32 + 31;
            for (; b > grp * 32; b--) {
                if (acc + s_hist[b] >= (unsigned)rem) break;
                acc += s_hist[b];
            }
            s_prefix = pfx | ((unsigned)b << shift);
            s_remaining = rem - (int)acc;
        }
        __syncthreads();
    }

    const float Tf = __uint_as_float(s_prefix);
    const float hi = Tf + EPS;
    const float lo = Tf - EPS;

    // Pass A: count certain ins (v > hi), collect boundary candidates
    {
        int local_cert = 0;
        for (int i = tid; i < DICT; i += 512) {
            float v = __uint_as_float(su[i]);
            if (v > hi) {
                local_cert++;
            } else if (v >= lo) {
                int p = atomicAdd(&s_ncand, 1);
                if (p < CAND_CAP) s_cand_idx[p] = i;
            }
        }
        atomicAdd(&s_ncert, local_cert);
    }
    __syncthreads();

    const int ncand = min(s_ncand, CAND_CAP);
    const int slots = K_TOP - s_ncert;

    if (ncand > 0) {
        for (int k = tid; k < ACT; k += 512)
            s_x[k] = x[(size_t)row * ACT + k] - b_dec[k];
        __syncthreads();

        // near-exact pre_act: fp64 lane chains + fp64 tree reduce
        for (int c = wid; c < ncand; c += 16) {
            const int m = s_cand_idx[c];
            const float* w = &W_enc[(size_t)m * ACT];
            double acc = 0.0;
            const int k0 = lane * (ACT / 32);
#pragma unroll 8
            for (int k = k0; k < k0 + ACT / 32; k++)
                acc = fma((double)s_x[k], (double)__ldg(&w[k]), acc);
#pragma unroll
            for (int off = 16; off; off >>= 1)
                acc += __shfl_down_sync(FULL, acc, off);
            if (lane == 0) {
                double v = acc + (double)__ldg(&b_enc[m]);
                s_cand_val[c] = v > 0.0 ? v : 0.0;
            }
        }
        __syncthreads();

        if (tid < ncand) {
            const double vi = s_cand_val[tid];
            const int ii = s_cand_idx[tid];
            int r = 0;
            for (int j = 0; j < ncand; j++) {
                double vj = s_cand_val[j];
                if (vj > vi || (vj == vi && s_cand_idx[j] < ii)) r++;
            }
            su[ii] = (r < slots) ? (__float_as_uint((float)vi) | 0x80000000u) : 0u;
        }
        __syncthreads();
    }

    // Pass D1: per-(chunk,warp) selection counts (no syncs inside)
#pragma unroll 4
    for (int c = 0; c < 64; c++) {
        int i = c * 512 + tid;
        unsigned u = su[i];
        bool sel = (u & 0x80000000u) || (__uint_as_float(u & 0x7fffffffu) > hi);
        unsigned b = __ballot_sync(FULL, sel);
        if (lane == 0) s_cntf[c * 16 + wid] = __popc(b);
    }
    __syncthreads();

    // hierarchical exclusive scan of 1024 counts (index order preserved)
    {
        int j0 = wid * 64;
        int a1 = s_cntf[j0 + lane];
        int a2 = s_cntf[j0 + 32 + lane];
        int s1 = a1, s2 = a2;
#pragma unroll
        for (int off = 1; off < 32; off <<= 1) {
            int t1 = __shfl_up_sync(FULL, s1, off);
            int t2 = __shfl_up_sync(FULL, s2, off);
            if (lane >= off) { s1 += t1; s2 += t2; }
        }
        int tot1 = __shfl_sync(FULL, s1, 31);
        int tot2 = __shfl_sync(FULL, s2, 31);
        s_excl[j0 + lane] = s1 - a1;
        s_excl[j0 + 32 + lane] = tot1 + s2 - a2;
        if (lane == 0) s_wtot[wid] = tot1 + tot2;
    }
    __syncthreads();
    if (wid == 0) {
        int v = (lane < 16) ? s_wtot[lane] : 0;
        int s = v;
#pragma unroll
        for (int off = 1; off < 16; off <<= 1) {
            int t = __shfl_up_sync(FULL, s, off);
            if (lane >= off) s += t;
        }
        if (lane < 16) s_wbase[lane] = s - v;
    }
    __syncthreads();

    // Pass D2: write z + compact (idx,val) lists, sync-free
    const unsigned lmask = (1u << lane) - 1u;
#pragma unroll 4
    for (int c = 0; c < 64; c++) {
        int i = c * 512 + tid;
        unsigned u = su[i];
        bool selc = (u & 0x80000000u) != 0u;
        float uv = __uint_as_float(u & 0x7fffffffu);
        bool sel = selc || (uv > hi);
        unsigned b = __ballot_sync(FULL, sel);
        zr[i] = sel ? uv : 0.f;
        if (sel) {
            int j = c * 16 + wid;
            int slot = s_wbase[j >> 6] + s_excl[j] + __popc(b & lmask);
            g_idxs[row * K_TOP + slot] = i;
            g_vals[row * K_TOP + slot] = uv;
        }
    }
}

// ---------------- decode: x_hat = sum_k vals * W_decTh[idx] + b_dec ------
__global__ void __launch_bounds__(256)
decode_kernel(const float* __restrict__ b_dec, float* __restrict__ xhat) {
    __shared__ int s_idx[K_TOP];
    __shared__ float s_val[K_TOP];
    const int row = blockIdx.x;
    const int tid = threadIdx.x;
    if (tid < K_TOP) {
        s_idx[tid] = g_idxs[row * K_TOP + tid];
        s_val[tid] = g_vals[row * K_TOP + tid];
    }
    __syncthreads();
    const int d0 = tid * 8;   // 8 contiguous outputs per thread
    float a[8];
#pragma unroll
    for (int j = 0; j < 8; j += 4) {
        float4 b4 = *(const float4*)&b_dec[d0 + j];
        a[j] = b4.x; a[j + 1] = b4.y; a[j + 2] = b4.z; a[j + 3] = b4.w;
    }
#pragma unroll 4
    for (int k = 0; k < K_TOP; k++) {
        const __half2* w = (const __half2*)&g_WdecTh[(size_t)s_idx[k] * ACT + d0];
        float v = s_val[k];
#pragma unroll
        for (int j = 0; j < 4; j++) {
            float2 f = __half22float2(w[j]);
            a[2 * j]     += v * f.x;
            a[2 * j + 1] += v * f.y;
        }
    }
    *(float4*)&xhat[(size_t)row * ACT + d0] =
        make_float4(a[0], a[1], a[2], a[3]);
    *(float4*)&xhat[(size_t)row * ACT + d0 + 4] =
        make_float4(a[4], a[5], a[6], a[7]);
}

// ---------------- launch ----------------
extern "C" void kernel_launch(void* const* d_in, const int* in_sizes, int n_in,
                              void* d_out, int out_size) {
    (void)in_sizes; (void)n_in; (void)out_size;
    const float* x     = (const float*)d_in[0];
    const float* W_enc = (const float*)d_in[1];
    const float* b_enc = (const float*)d_in[2];
    const float* W_dec = (const float*)d_in[3];
    const float* b_dec = (const float*)d_in[4];
    float* xhat = (float*)d_out;
    float* z    = xhat + (size_t)BATCH * ACT;

    prep_a_kernel<<<(BATCH * (size_t)ACT) / 256, 256>>>(x, b_dec);
    prep_b_kernel<<<(DICT * (size_t)ACT) / 1024, 256>>>(W_enc);
    transpose_kernel<<<dim3(DICT / 32, ACT / 32), dim3(32, 8)>>>(W_dec);

    cudaFuncSetAttribute(encode_gemm_kernel,
                         cudaFuncAttributeMaxDynamicSharedMemorySize, GEMM_SMEM);
    // batch-fastest grid: one wave shares B tiles via L2 (B DRAM read ~once)
    encode_gemm_kernel<<<dim3(BATCH / BM, DICT / BN), 256, GEMM_SMEM>>>(b_enc, z);

    cudaFuncSetAttribute(topk_kernel,
                         cudaFuncAttributeMaxDynamicSharedMemorySize, DICT * 4);
    topk_kernel<<<BATCH, 512, DICT * 4>>>(x, W_enc, b_enc, b_dec, z);

    decode_kernel<<<BATCH, 256>>>(b_dec, xhat);
}

// round 7
// speedup vs baseline: 2.3018x; 1.0570x over previous
#include <cuda_runtime.h>
#include <cuda_fp16.h>
#include <cstdint>

#define BATCH 4096
#define ACT   2048
#define DICT  32768
#define K_TOP 64
#define EPS   5e-3f
#define CAND_CAP 256

// ---------------- device scratch (static, no allocations) ----------------
__device__ __half g_Af[(size_t)BATCH * ACT];
__device__ __half g_Bf[(size_t)DICT * ACT];
__device__ __half g_WdecTh[(size_t)DICT * ACT];   // [DICT][ACT] fp16
__device__ float  g_vals[BATCH * K_TOP];
__device__ int    g_idxs[BATCH * K_TOP];

// ---------------- prep: fp32 -> fp16 ----------------
__global__ void prep_a_kernel(const float* __restrict__ x,
                              const float* __restrict__ b_dec) {
    size_t i = (size_t)blockIdx.x * blockDim.x + threadIdx.x;
    g_Af[i] = __float2half(x[i] - __ldg(&b_dec[i & (ACT - 1)]));
}

__global__ void prep_b_kernel(const float* __restrict__ W) {
    size_t i4 = ((size_t)blockIdx.x * blockDim.x + threadIdx.x) * 4;
    float4 v = *(const float4*)&W[i4];
    __half2* o = (__half2*)&g_Bf[i4];
    o[0] = __floats2half2_rn(v.x, v.y);
    o[1] = __floats2half2_rn(v.z, v.w);
}

// ---------------- transpose W_dec [ACT][DICT] -> g_WdecTh [DICT][ACT] ----
__global__ void transpose_kernel(const float* __restrict__ W) {
    __shared__ float tile[32][33];
    int bx = blockIdx.x * 32;   // dict dim
    int by = blockIdx.y * 32;   // act dim
    int tx = threadIdx.x, ty = threadIdx.y;  // 32 x 8
#pragma unroll
    for (int j = 0; j < 32; j += 8)
        tile[ty + j][tx] = W[(size_t)(by + ty + j) * DICT + bx + tx];
    __syncthreads();
#pragma unroll
    for (int j = 0; j < 32; j += 8)
        g_WdecTh[(size_t)(bx + ty + j) * ACT + by + tx] =
            __float2half(tile[tx][ty + j]);
}

// ---------------- encode GEMM: z = relu((x-b_dec) @ W_enc^T + b_enc) -----
// single fp16 term, fp32 accumulate; 128x128 tile, BK=64, 2-stage, 2 CTA/SM
// fragments via ldmatrix.x4 (4x fewer shared-pipe instructions than LDS.32)
#define BM 128
#define BN 128
#define BK 64
#define SSTR 72                       // fp16 elems per smem row (BK + 8 pad)
#define STAGE_ELEMS (128 * SSTR)      // per matrix per stage (9216)
#define NSTAGE 2
#define GEMM_SMEM (NSTAGE * 2 * STAGE_ELEMS * 2)   // 73728 B -> 2 CTA/SM

__device__ __forceinline__ void cp16(unsigned saddr, const void* g) {
    asm volatile("cp.async.cg.shared.global [%0], [%1], 16;\n" ::"r"(saddr), "l"(g));
}

#define LDSM4(r, a)                                                          \
    asm volatile(                                                            \
        "ldmatrix.sync.aligned.m8n8.x4.shared.b16 {%0,%1,%2,%3}, [%4];"      \
        : "=r"((r)[0]), "=r"((r)[1]), "=r"((r)[2]), "=r"((r)[3])             \
        : "r"(a))

__device__ __forceinline__ void mma_f16(float* c, const uint32_t* a,
                                        const uint32_t* b) {
    asm volatile(
        "mma.sync.aligned.m16n8k16.row.col.f32.f16.f16.f32 "
        "{%0,%1,%2,%3},{%4,%5,%6,%7},{%8,%9},{%0,%1,%2,%3};\n"
        : "+f"(c[0]), "+f"(c[1]), "+f"(c[2]), "+f"(c[3])
        : "r"(a[0]), "r"(a[1]), "r"(a[2]), "r"(a[3]), "r"(b[0]), "r"(b[1]));
}

__global__ void __launch_bounds__(256, 2)
encode_gemm_kernel(const float* __restrict__ b_enc, float* __restrict__ z) {
    extern __shared__ __align__(16) __half sm[];

    const int tid = threadIdx.x;
    const int by = blockIdx.x * BM;   // batch offset (fast grid dim)
    const int bx = blockIdx.y * BN;   // dict offset
    const int warp = tid >> 5, lane = tid & 31;
    const int wm = (warp & 3) * 32;
    const int wn = (warp >> 2) * 64;
    const int g = lane >> 2, tig = lane & 3;

    const unsigned uS = (unsigned)__cvta_generic_to_shared(sm);

    // ldmatrix per-lane address components
    const int aRow = wm + (lane & 15);            // + mi*16
    const int aCol = (lane & 16) >> 1;            // 0 or 8 (k offset)
    const int bRow = wn + (lane & 7) + ((lane & 16) >> 1);   // + p*16
    const int bCol = lane & 8;                    // 0 or 8 (k offset)

    float acc[2][8][4];
#pragma unroll
    for (int mi = 0; mi < 2; mi++)
#pragma unroll
        for (int ni = 0; ni < 8; ni++)
#pragma unroll
            for (int q = 0; q < 4; q++) acc[mi][ni][q] = 0.f;

    const int KT = ACT / BK;   // 32

#define LOAD_STAGE(stage, kt)                                                  \
    {                                                                          \
        const int koff = (kt) * BK;                                            \
        _Pragma("unroll")                                                      \
        for (int r = 0; r < 4; r++) {                                          \
            int id = tid + r * 256;                                            \
            int row = id >> 3;                                                 \
            int ch = (id & 7) * 8;                                             \
            unsigned sa =                                                      \
                (unsigned)(((stage) * 2 * STAGE_ELEMS + row * SSTR + ch) * 2); \
            cp16(uS + sa, &g_Af[(size_t)(by + row) * ACT + koff + ch]);        \
            cp16(uS + sa + STAGE_ELEMS * 2,                                    \
                 &g_Bf[(size_t)(bx + row) * ACT + koff + ch]);                 \
        }                                                                      \
    }

    LOAD_STAGE(0, 0);
    asm volatile("cp.async.commit_group;\n");

    for (int kt = 0; kt < KT; kt++) {
        const int cur = kt & 1;
        if (kt + 1 < KT) {
            LOAD_STAGE((kt + 1) & 1, kt + 1);
            asm volatile("cp.async.commit_group;\n");
            asm volatile("cp.async.wait_group 1;\n");
        } else {
            asm volatile("cp.async.wait_group 0;\n");
        }
        __syncthreads();

        const unsigned uA = uS + (unsigned)(cur * 2 * STAGE_ELEMS * 2);
        const unsigned uB = uA + STAGE_ELEMS * 2;
#pragma unroll
        for (int ks = 0; ks < 4; ks++) {
            const int kcol = ks * 16;
            uint32_t af[2][4];
#pragma unroll
            for (int mi = 0; mi < 2; mi++) {
                unsigned ad =
                    uA + (unsigned)(((aRow + mi * 16) * SSTR + kcol + aCol) * 2);
                LDSM4(af[mi], ad);
            }
            uint32_t bf[8][2];
#pragma unroll
            for (int p = 0; p < 4; p++) {
                unsigned bd =
                    uB + (unsigned)(((bRow + p * 16) * SSTR + kcol + bCol) * 2);
                uint32_t r[4];
                LDSM4(r, bd);
                bf[2 * p][0] = r[0];
                bf[2 * p][1] = r[1];
                bf[2 * p + 1][0] = r[2];
                bf[2 * p + 1][1] = r[3];
            }
#pragma unroll
            for (int ni = 0; ni < 8; ni++)
#pragma unroll
                for (int mi = 0; mi < 2; mi++)
                    mma_f16(acc[mi][ni], af[mi], bf[ni]);
        }
        __syncthreads();
    }

    // epilogue: +b_enc, relu, write straight into z region of d_out
#pragma unroll
    for (int mi = 0; mi < 2; mi++) {
        int r = by + wm + mi * 16 + g;
#pragma unroll
        for (int ni = 0; ni < 8; ni++) {
            int c = bx + wn + ni * 8 + tig * 2;
            float be0 = __ldg(&b_enc[c]);
            float be1 = __ldg(&b_enc[c + 1]);
            float v0 = fmaxf(acc[mi][ni][0] + be0, 0.f);
            float v1 = fmaxf(acc[mi][ni][1] + be1, 0.f);
            float v2 = fmaxf(acc[mi][ni][2] + be0, 0.f);
            float v3 = fmaxf(acc[mi][ni][3] + be1, 0.f);
            *(float2*)&z[(size_t)r * DICT + c] = make_float2(v0, v1);
            *(float2*)&z[(size_t)(r + 8) * DICT + c] = make_float2(v2, v3);
        }
    }
}

// ---------------- per-row top-K: radix select + fp64-exact boundary refine
__global__ void __launch_bounds__(512) topk_kernel(
    const float* __restrict__ x, const float* __restrict__ W_enc,
    const float* __restrict__ b_enc, const float* __restrict__ b_dec,
    float* __restrict__ z) {
    extern __shared__ __align__(16) unsigned su[];   // DICT uints (128 KB)
    __shared__ float s_x[ACT];
    __shared__ unsigned s_hist[256];
    __shared__ unsigned s_gsum[8];
    __shared__ unsigned s_prefix;
    __shared__ int s_remaining;
    __shared__ int s_ncand, s_ncert;
    __shared__ int s_cand_idx[CAND_CAP];
    __shared__ double s_cand_val[CAND_CAP];
    __shared__ int s_cntf[1024];
    __shared__ int s_excl[1024];
    __shared__ int s_wtot[16], s_wbase[16];

    const unsigned FULL = 0xffffffffu;
    const int row = blockIdx.x;
    const int tid = threadIdx.x;
    const int lane = tid & 31, wid = tid >> 5;
    float* zr = z + (size_t)row * DICT;

    for (int i = tid; i < DICT; i += 512) {
        float v = zr[i];
        su[i] = __float_as_uint(fmaxf(v, 0.f));
    }
    if (tid == 0) { s_prefix = 0u; s_remaining = K_TOP; s_ncand = 0; s_ncert = 0; }
    __syncthreads();

#pragma unroll
    for (int shift = 24; shift >= 0; shift -= 8) {
        if (tid < 256) s_hist[tid] = 0u;
        __syncthreads();
        unsigned pfx = s_prefix;
        for (int i = tid; i < DICT; i += 512) {
            unsigned u = su[i];
            bool ok = (shift == 24) ? true
                                    : ((u >> (shift + 8)) == (pfx >> (shift + 8)));
            if (ok) atomicAdd(&s_hist[(u >> shift) & 255u], 1u);
        }
        __syncthreads();
        if (tid < 256) {
            unsigned v = s_hist[tid];
#pragma unroll
            for (int off = 16; off; off >>= 1)
                v += __shfl_down_sync(FULL, v, off);
            if (lane == 0) s_gsum[tid >> 5] = v;
        }
        __syncthreads();
        if (tid == 0) {
            int rem = s_remaining;
            unsigned acc = 0;
            int grp = 7;
            for (; grp > 0; grp--) {
                if (acc + s_gsum[grp] >= (unsigned)rem) break;
                acc += s_gsum[grp];
            }
            int b = grp * 32 + 31;
            for (; b > grp * 32; b--) {
                if (acc + s_hist[b] >= (unsigned)rem) break;
                acc += s_hist[b];
            }
            s_prefix = pfx | ((unsigned)b << shift);
            s_remaining = rem - (int)acc;
        }
        __syncthreads();
    }

    const float Tf = __uint_as_float(s_prefix);
    const float hi = Tf + EPS;
    const float lo = Tf - EPS;

    {
        int local_cert = 0;
        for (int i = tid; i < DICT; i += 512) {
            float v = __uint_as_float(su[i]);
            if (v > hi) {
                local_cert++;
            } else if (v >= lo) {
                int p = atomicAdd(&s_ncand, 1);
                if (p < CAND_CAP) s_cand_idx[p] = i;
            }
        }
        atomicAdd(&s_ncert, local_cert);
    }
    __syncthreads();

    const int ncand = min(s_ncand, CAND_CAP);
    const int slots = K_TOP - s_ncert;

    if (ncand > 0) {
        for (int k = tid; k < ACT; k += 512)
            s_x[k] = x[(size_t)row * ACT + k] - b_dec[k];
        __syncthreads();

        for (int c = wid; c < ncand; c += 16) {
            const int m = s_cand_idx[c];
            const float* w = &W_enc[(size_t)m * ACT];
            double acc = 0.0;
            const int k0 = lane * (ACT / 32);
#pragma unroll 8
            for (int k = k0; k < k0 + ACT / 32; k++)
                acc = fma((double)s_x[k], (double)__ldg(&w[k]), acc);
#pragma unroll
            for (int off = 16; off; off >>= 1)
                acc += __shfl_down_sync(FULL, acc, off);
            if (lane == 0) {
                double v = acc + (double)__ldg(&b_enc[m]);
                s_cand_val[c] = v > 0.0 ? v : 0.0;
            }
        }
        __syncthreads();

        if (tid < ncand) {
            const double vi = s_cand_val[tid];
            const int ii = s_cand_idx[tid];
            int r = 0;
            for (int j = 0; j < ncand; j++) {
                double vj = s_cand_val[j];
                if (vj > vi || (vj == vi && s_cand_idx[j] < ii)) r++;
            }
            su[ii] = (r < slots) ? (__float_as_uint((float)vi) | 0x80000000u) : 0u;
        }
        __syncthreads();
    }

#pragma unroll 4
    for (int c = 0; c < 64; c++) {
        int i = c * 512 + tid;
        unsigned u = su[i];
        bool sel = (u & 0x80000000u) || (__uint_as_float(u & 0x7fffffffu) > hi);
        unsigned b = __ballot_sync(FULL, sel);
        if (lane == 0) s_cntf[c * 16 + wid] = __popc(b);
    }
    __syncthreads();

    {
        int j0 = wid * 64;
        int a1 = s_cntf[j0 + lane];
        int a2 = s_cntf[j0 + 32 + lane];
        int s1 = a1, s2 = a2;
#pragma unroll
        for (int off = 1; off < 32; off <<= 1) {
            int t1 = __shfl_up_sync(FULL, s1, off);
            int t2 = __shfl_up_sync(FULL, s2, off);
            if (lane >= off) { s1 += t1; s2 += t2; }
        }
        int tot1 = __shfl_sync(FULL, s1, 31);
        int tot2 = __shfl_sync(FULL, s2, 31);
        s_excl[j0 + lane] = s1 - a1;
        s_excl[j0 + 32 + lane] = tot1 + s2 - a2;
        if (lane == 0) s_wtot[wid] = tot1 + tot2;
    }
    __syncthreads();
    if (wid == 0) {
        int v = (lane < 16) ? s_wtot[lane] : 0;
        int s = v;
#pragma unroll
        for (int off = 1; off < 16; off <<= 1) {
            int t = __shfl_up_sync(FULL, s, off);
            if (lane >= off) s += t;
        }
        if (lane < 16) s_wbase[lane] = s - v;
    }
    __syncthreads();

    const unsigned lmask = (1u << lane) - 1u;
#pragma unroll 4
    for (int c = 0; c < 64; c++) {
        int i = c * 512 + tid;
        unsigned u = su[i];
        bool selc = (u & 0x80000000u) != 0u;
        float uv = __uint_as_float(u & 0x7fffffffu);
        bool sel = selc || (uv > hi);
        unsigned b = __ballot_sync(FULL, sel);
        zr[i] = sel ? uv : 0.f;
        if (sel) {
            int j = c * 16 + wid;
            int slot = s_wbase[j >> 6] + s_excl[j] + __popc(b & lmask);
            g_idxs[row * K_TOP + slot] = i;
            g_vals[row * K_TOP + slot] = uv;
        }
    }
}

// ---------------- decode: x_hat = sum_k vals * W_decTh[idx] + b_dec ------
__global__ void __launch_bounds__(256)
decode_kernel(const float* __restrict__ b_dec, float* __restrict__ xhat) {
    __shared__ int s_idx[K_TOP];
    __shared__ float s_val[K_TOP];
    const int row = blockIdx.x;
    const int tid = threadIdx.x;
    if (tid < K_TOP) {
        s_idx[tid] = g_idxs[row * K_TOP + tid];
        s_val[tid] = g_vals[row * K_TOP + tid];
    }
    __syncthreads();
    const int d0 = tid * 8;
    float a[8];
#pragma unroll
    for (int j = 0; j < 8; j += 4) {
        float4 b4 = *(const float4*)&b_dec[d0 + j];
        a[j] = b4.x; a[j + 1] = b4.y; a[j + 2] = b4.z; a[j + 3] = b4.w;
    }
#pragma unroll 4
    for (int k = 0; k < K_TOP; k++) {
        const __half2* w = (const __half2*)&g_WdecTh[(size_t)s_idx[k] * ACT + d0];
        float v = s_val[k];
#pragma unroll
        for (int j = 0; j < 4; j++) {
            float2 f = __half22float2(w[j]);
            a[2 * j]     += v * f.x;
            a[2 * j + 1] += v * f.y;
        }
    }
    *(float4*)&xhat[(size_t)row * ACT + d0] =
        make_float4(a[0], a[1], a[2], a[3]);
    *(float4*)&xhat[(size_t)row * ACT + d0 + 4] =
        make_float4(a[4], a[5], a[6], a[7]);
}

// ---------------- launch ----------------
extern "C" void kernel_launch(void* const* d_in, const int* in_sizes, int n_in,
                              void* d_out, int out_size) {
    (void)in_sizes; (void)n_in; (void)out_size;
    const float* x     = (const float*)d_in[0];
    const float* W_enc = (const float*)d_in[1];
    const float* b_enc = (const float*)d_in[2];
    const float* W_dec = (const float*)d_in[3];
    const float* b_dec = (const float*)d_in[4];
    float* xhat = (float*)d_out;
    float* z    = xhat + (size_t)BATCH * ACT;

    prep_a_kernel<<<(BATCH * (size_t)ACT) / 256, 256>>>(x, b_dec);
    prep_b_kernel<<<(DICT * (size_t)ACT) / 1024, 256>>>(W_enc);
    transpose_kernel<<<dim3(DICT / 32, ACT / 32), dim3(32, 8)>>>(W_dec);

    cudaFuncSetAttribute(encode_gemm_kernel,
                         cudaFuncAttributeMaxDynamicSharedMemorySize, GEMM_SMEM);
    encode_gemm_kernel<<<dim3(BATCH / BM, DICT / BN), 256, GEMM_SMEM>>>(b_enc, z);

    cudaFuncSetAttribute(topk_kernel,
                         cudaFuncAttributeMaxDynamicSharedMemorySize, DICT * 4);
    topk_kernel<<<BATCH, 512, DICT * 4>>>(x, W_enc, b_enc, b_dec, z);

    decode_kernel<<<BATCH, 256>>>(b_dec, xhat);
}

// round 8
// speedup vs baseline: 2.3373x; 1.0154x over previous
#include <cuda_runtime.h>
#include <cuda_fp16.h>
#include <cstdint>

#define BATCH 4096
#define ACT   2048
#define DICT  32768
#define K_TOP 64
#define EPS   5e-3f
#define CAND_CAP 256

// ---------------- device scratch (static, no allocations) ----------------
__device__ __half g_Af[(size_t)BATCH * ACT];
__device__ __half g_Bf[(size_t)DICT * ACT];
__device__ __half g_WdecTh[(size_t)DICT * ACT];   // [DICT][ACT] fp16
__device__ float  g_vals[BATCH * K_TOP];
__device__ int    g_idxs[BATCH * K_TOP];

// ---------------- prep: fp32 -> fp16 ----------------
__global__ void prep_a_kernel(const float* __restrict__ x,
                              const float* __restrict__ b_dec) {
    size_t i4 = ((size_t)blockIdx.x * blockDim.x + threadIdx.x) * 4;
    float4 v = *(const float4*)&x[i4];
    int c = (int)(i4 & (ACT - 1));
    float4 b = *(const float4*)&b_dec[c];
    __half2* o = (__half2*)&g_Af[i4];
    o[0] = __floats2half2_rn(v.x - b.x, v.y - b.y);
    o[1] = __floats2half2_rn(v.z - b.z, v.w - b.w);
}

__global__ void prep_b_kernel(const float* __restrict__ W) {
    size_t i4 = ((size_t)blockIdx.x * blockDim.x + threadIdx.x) * 4;
    float4 v = *(const float4*)&W[i4];
    __half2* o = (__half2*)&g_Bf[i4];
    o[0] = __floats2half2_rn(v.x, v.y);
    o[1] = __floats2half2_rn(v.z, v.w);
}

// ---------------- transpose W_dec [ACT][DICT] -> g_WdecTh [DICT][ACT] ----
__global__ void transpose_kernel(const float* __restrict__ W) {
    __shared__ float tile[32][33];
    int bx = blockIdx.x * 32;   // dict dim
    int by = blockIdx.y * 32;   // act dim
    int tx = threadIdx.x, ty = threadIdx.y;  // 32 x 8
#pragma unroll
    for (int j = 0; j < 32; j += 8)
        tile[ty + j][tx] = W[(size_t)(by + ty + j) * DICT + bx + tx];
    __syncthreads();
#pragma unroll
    for (int j = 0; j < 32; j += 8)
        g_WdecTh[(size_t)(bx + ty + j) * ACT + by + tx] =
            __float2half(tile[tx][ty + j]);
}

// ---------------- encode GEMM: z = relu((x-b_dec) @ W_enc^T + b_enc) -----
// single fp16 term, fp32 accumulate; 128x128 tile, BK=64,
// 3-stage cp.async pipeline, ONE __syncthreads per k-tile, 2 CTA/SM
#define BM 128
#define BN 128
#define BK 64
#define SSTR 72                       // fp16 elems per smem row (BK + 8 pad)
#define STAGE_ELEMS (128 * SSTR)      // per matrix per stage (9216)
#define NSTAGE 3
#define GEMM_SMEM (NSTAGE * 2 * STAGE_ELEMS * 2)   // 110592 B; x2 CTA = 216KB

__device__ __forceinline__ void cp16(unsigned saddr, const void* g) {
    asm volatile("cp.async.cg.shared.global [%0], [%1], 16;\n" ::"r"(saddr), "l"(g));
}

#define LDSM4(r, a)                                                          \
    asm volatile(                                                            \
        "ldmatrix.sync.aligned.m8n8.x4.shared.b16 {%0,%1,%2,%3}, [%4];"      \
        : "=r"((r)[0]), "=r"((r)[1]), "=r"((r)[2]), "=r"((r)[3])             \
        : "r"(a))

__device__ __forceinline__ void mma_f16(float* c, const uint32_t* a,
                                        const uint32_t* b) {
    asm volatile(
        "mma.sync.aligned.m16n8k16.row.col.f32.f16.f16.f32 "
        "{%0,%1,%2,%3},{%4,%5,%6,%7},{%8,%9},{%0,%1,%2,%3};\n"
        : "+f"(c[0]), "+f"(c[1]), "+f"(c[2]), "+f"(c[3])
        : "r"(a[0]), "r"(a[1]), "r"(a[2]), "r"(a[3]), "r"(b[0]), "r"(b[1]));
}

__global__ void __launch_bounds__(256, 2)
encode_gemm_kernel(const float* __restrict__ b_enc, float* __restrict__ z) {
    extern __shared__ __align__(16) __half sm[];

    const int tid = threadIdx.x;
    const int by = blockIdx.x * BM;   // batch offset (fast grid dim)
    const int bx = blockIdx.y * BN;   // dict offset
    const int warp = tid >> 5, lane = tid & 31;
    const int wm = (warp & 3) * 32;
    const int wn = (warp >> 2) * 64;
    const int g = lane >> 2, tig = lane & 3;

    const unsigned uS = (unsigned)__cvta_generic_to_shared(sm);

    // ldmatrix per-lane address components
    const int aRow = wm + (lane & 15);
    const int aCol = (lane & 16) >> 1;
    const int bRow = wn + (lane & 7) + ((lane & 16) >> 1);
    const int bCol = lane & 8;

    float acc[2][8][4];
#pragma unroll
    for (int mi = 0; mi < 2; mi++)
#pragma unroll
        for (int ni = 0; ni < 8; ni++)
#pragma unroll
            for (int q = 0; q < 4; q++) acc[mi][ni][q] = 0.f;

    const int KT = ACT / BK;   // 32

#define LOAD_STAGE(stage, kt)                                                  \
    {                                                                          \
        const int koff = (kt) * BK;                                            \
        _Pragma("unroll")                                                      \
        for (int r = 0; r < 4; r++) {                                          \
            int id = tid + r * 256;                                            \
            int row = id >> 3;                                                 \
            int ch = (id & 7) * 8;                                             \
            unsigned sa =                                                      \
                (unsigned)(((stage) * 2 * STAGE_ELEMS + row * SSTR + ch) * 2); \
            cp16(uS + sa, &g_Af[(size_t)(by + row) * ACT + koff + ch]);        \
            cp16(uS + sa + STAGE_ELEMS * 2,                                    \
                 &g_Bf[(size_t)(bx + row) * ACT + koff + ch]);                 \
        }                                                                      \
    }

    LOAD_STAGE(0, 0);
    asm volatile("cp.async.commit_group;\n");
    LOAD_STAGE(1, 1);
    asm volatile("cp.async.commit_group;\n");

    int cur = 0, nxt = 2;
    for (int kt = 0; kt < KT; kt++) {
        if (kt + 2 < KT) {
            asm volatile("cp.async.wait_group 1;\n");   // stage kt ready
        } else {
            asm volatile("cp.async.wait_group 0;\n");
        }
        __syncthreads();   // all warps done reading stage (kt-1); stage kt visible

        // prefetch stage kt+2 into the buffer freed at kt-1 (safe post-sync)
        if (kt + 2 < KT) {
            LOAD_STAGE(nxt, kt + 2);
            asm volatile("cp.async.commit_group;\n");
        }

        const unsigned uA = uS + (unsigned)(cur * 2 * STAGE_ELEMS * 2);
        const unsigned uB = uA + STAGE_ELEMS * 2;
#pragma unroll
        for (int ks = 0; ks < 4; ks++) {
            const int kcol = ks * 16;
            uint32_t af[2][4];
#pragma unroll
            for (int mi = 0; mi < 2; mi++) {
                unsigned ad =
                    uA + (unsigned)(((aRow + mi * 16) * SSTR + kcol + aCol) * 2);
                LDSM4(af[mi], ad);
            }
            uint32_t bf[8][2];
#pragma unroll
            for (int p = 0; p < 4; p++) {
                unsigned bd =
                    uB + (unsigned)(((bRow + p * 16) * SSTR + kcol + bCol) * 2);
                uint32_t r[4];
                LDSM4(r, bd);
                bf[2 * p][0] = r[0];
                bf[2 * p][1] = r[1];
                bf[2 * p + 1][0] = r[2];
                bf[2 * p + 1][1] = r[3];
            }
#pragma unroll
            for (int ni = 0; ni < 8; ni++)
#pragma unroll
                for (int mi = 0; mi < 2; mi++)
                    mma_f16(acc[mi][ni], af[mi], bf[ni]);
        }
        cur = (cur == 2) ? 0 : cur + 1;
        nxt = (nxt == 2) ? 0 : nxt + 1;
    }

    // epilogue: +b_enc, relu, write straight into z region of d_out
#pragma unroll
    for (int mi = 0; mi < 2; mi++) {
        int r = by + wm + mi * 16 + g;
#pragma unroll
        for (int ni = 0; ni < 8; ni++) {
            int c = bx + wn + ni * 8 + tig * 2;
            float be0 = __ldg(&b_enc[c]);
            float be1 = __ldg(&b_enc[c + 1]);
            float v0 = fmaxf(acc[mi][ni][0] + be0, 0.f);
            float v1 = fmaxf(acc[mi][ni][1] + be1, 0.f);
            float v2 = fmaxf(acc[mi][ni][2] + be0, 0.f);
            float v3 = fmaxf(acc[mi][ni][3] + be1, 0.f);
            *(float2*)&z[(size_t)r * DICT + c] = make_float2(v0, v1);
            *(float2*)&z[(size_t)(r + 8) * DICT + c] = make_float2(v2, v3);
        }
    }
}

// ---------------- per-row top-K: radix select + fp64-exact boundary refine
__global__ void __launch_bounds__(512) topk_kernel(
    const float* __restrict__ x, const float* __restrict__ W_enc,
    const float* __restrict__ b_enc, const float* __restrict__ b_dec,
    float* __restrict__ z) {
    extern __shared__ __align__(16) unsigned su[];   // DICT uints (128 KB)
    __shared__ float s_x[ACT];
    __shared__ unsigned s_hist[256];
    __shared__ unsigned s_gsum[8];
    __shared__ unsigned s_prefix;
    __shared__ int s_remaining;
    __shared__ int s_ncand, s_ncert;
    __shared__ int s_cand_idx[CAND_CAP];
    __shared__ double s_cand_val[CAND_CAP];
    __shared__ int s_cntf[1024];
    __shared__ int s_excl[1024];
    __shared__ int s_wtot[16], s_wbase[16];

    const unsigned FULL = 0xffffffffu;
    const int row = blockIdx.x;
    const int tid = threadIdx.x;
    const int lane = tid & 31, wid = tid >> 5;
    float* zr = z + (size_t)row * DICT;

    for (int i = tid; i < DICT; i += 512) {
        float v = zr[i];
        su[i] = __float_as_uint(fmaxf(v, 0.f));
    }
    if (tid == 0) { s_prefix = 0u; s_remaining = K_TOP; s_ncand = 0; s_ncert = 0; }
    __syncthreads();

#pragma unroll
    for (int shift = 24; shift >= 0; shift -= 8) {
        if (tid < 256) s_hist[tid] = 0u;
        __syncthreads();
        unsigned pfx = s_prefix;
        for (int i = tid; i < DICT; i += 512) {
            unsigned u = su[i];
            bool ok = (shift == 24) ? true
                                    : ((u >> (shift + 8)) == (pfx >> (shift + 8)));
            if (ok) atomicAdd(&s_hist[(u >> shift) & 255u], 1u);
        }
        __syncthreads();
        if (tid < 256) {
            unsigned v = s_hist[tid];
#pragma unroll
            for (int off = 16; off; off >>= 1)
                v += __shfl_down_sync(FULL, v, off);
            if (lane == 0) s_gsum[tid >> 5] = v;
        }
        __syncthreads();
        if (tid == 0) {
            int rem = s_remaining;
            unsigned acc = 0;
            int grp = 7;
            for (; grp > 0; grp--) {
                if (acc + s_gsum[grp] >= (unsigned)rem) break;
                acc += s_gsum[grp];
            }
            int b = grp * 32 + 31;
            for (; b > grp * 32; b--) {
                if (acc + s_hist[b] >= (unsigned)rem) break;
                acc += s_hist[b];
            }
            s_prefix = pfx | ((unsigned)b << shift);
            s_remaining = rem - (int)acc;
        }
        __syncthreads();
    }

    const float Tf = __uint_as_float(s_prefix);
    const float hi = Tf + EPS;
    const float lo = Tf - EPS;

    {
        int local_cert = 0;
        for (int i = tid; i < DICT; i += 512) {
            float v = __uint_as_float(su[i]);
            if (v > hi) {
                local_cert++;
            } else if (v >= lo) {
                int p = atomicAdd(&s_ncand, 1);
                if (p < CAND_CAP) s_cand_idx[p] = i;
            }
        }
        atomicAdd(&s_ncert, local_cert);
    }
    __syncthreads();

    const int ncand = min(s_ncand, CAND_CAP);
    const int slots = K_TOP - s_ncert;

    if (ncand > 0) {
        for (int k = tid; k < ACT; k += 512)
            s_x[k] = x[(size_t)row * ACT + k] - b_dec[k];
        __syncthreads();

        for (int c = wid; c < ncand; c += 16) {
            const int m = s_cand_idx[c];
            const float* w = &W_enc[(size_t)m * ACT];
            double acc = 0.0;
            const int k0 = lane * (ACT / 32);
#pragma unroll 8
            for (int k = k0; k < k0 + ACT / 32; k++)
                acc = fma((double)s_x[k], (double)__ldg(&w[k]), acc);
#pragma unroll
            for (int off = 16; off; off >>= 1)
                acc += __shfl_down_sync(FULL, acc, off);
            if (lane == 0) {
                double v = acc + (double)__ldg(&b_enc[m]);
                s_cand_val[c] = v > 0.0 ? v : 0.0;
            }
        }
        __syncthreads();

        if (tid < ncand) {
            const double vi = s_cand_val[tid];
            const int ii = s_cand_idx[tid];
            int r = 0;
            for (int j = 0; j < ncand; j++) {
                double vj = s_cand_val[j];
                if (vj > vi || (vj == vi && s_cand_idx[j] < ii)) r++;
            }
            su[ii] = (r < slots) ? (__float_as_uint((float)vi) | 0x80000000u) : 0u;
        }
        __syncthreads();
    }

#pragma unroll 4
    for (int c = 0; c < 64; c++) {
        int i = c * 512 + tid;
        unsigned u = su[i];
        bool sel = (u & 0x80000000u) || (__uint_as_float(u & 0x7fffffffu) > hi);
        unsigned b = __ballot_sync(FULL, sel);
        if (lane == 0) s_cntf[c * 16 + wid] = __popc(b);
    }
    __syncthreads();

    {
        int j0 = wid * 64;
        int a1 = s_cntf[j0 + lane];
        int a2 = s_cntf[j0 + 32 + lane];
        int s1 = a1, s2 = a2;
#pragma unroll
        for (int off = 1; off < 32; off <<= 1) {
            int t1 = __shfl_up_sync(FULL, s1, off);
            int t2 = __shfl_up_sync(FULL, s2, off);
            if (lane >= off) { s1 += t1; s2 += t2; }
        }
        int tot1 = __shfl_sync(FULL, s1, 31);
        int tot2 = __shfl_sync(FULL, s2, 31);
        s_excl[j0 + lane] = s1 - a1;
        s_excl[j0 + 32 + lane] = tot1 + s2 - a2;
        if (lane == 0) s_wtot[wid] = tot1 + tot2;
    }
    __syncthreads();
    if (wid == 0) {
        int v = (lane < 16) ? s_wtot[lane] : 0;
        int s = v;
#pragma unroll
        for (int off = 1; off < 16; off <<= 1) {
            int t = __shfl_up_sync(FULL, s, off);
            if (lane >= off) s += t;
        }
        if (lane < 16) s_wbase[lane] = s - v;
    }
    __syncthreads();

    const unsigned lmask = (1u << lane) - 1u;
#pragma unroll 4
    for (int c = 0; c < 64; c++) {
        int i = c * 512 + tid;
        unsigned u = su[i];
        bool selc = (u & 0x80000000u) != 0u;
        float uv = __uint_as_float(u & 0x7fffffffu);
        bool sel = selc || (uv > hi);
        unsigned b = __ballot_sync(FULL, sel);
        zr[i] = sel ? uv : 0.f;
        if (sel) {
            int j = c * 16 + wid;
            int slot = s_wbase[j >> 6] + s_excl[j] + __popc(b & lmask);
            g_idxs[row * K_TOP + slot] = i;
            g_vals[row * K_TOP + slot] = uv;
        }
    }
}

// ---------------- decode: x_hat = sum_k vals * W_decTh[idx] + b_dec ------
__global__ void __launch_bounds__(256)
decode_kernel(const float* __restrict__ b_dec, float* __restrict__ xhat) {
    __shared__ int s_idx[K_TOP];
    __shared__ float s_val[K_TOP];
    const int row = blockIdx.x;
    const int tid = threadIdx.x;
    if (tid < K_TOP) {
        s_idx[tid] = g_idxs[row * K_TOP + tid];
        s_val[tid] = g_vals[row * K_TOP + tid];
    }
    __syncthreads();
    const int d0 = tid * 8;
    float a[8];
#pragma unroll
    for (int j = 0; j < 8; j += 4) {
        float4 b4 = *(const float4*)&b_dec[d0 + j];
        a[j] = b4.x; a[j + 1] = b4.y; a[j + 2] = b4.z; a[j + 3] = b4.w;
    }
#pragma unroll 4
    for (int k = 0; k < K_TOP; k++) {
        const __half2* w = (const __half2*)&g_WdecTh[(size_t)s_idx[k] * ACT + d0];
        float v = s_val[k];
#pragma unroll
        for (int j = 0; j < 4; j++) {
            float2 f = __half22float2(w[j]);
            a[2 * j]     += v * f.x;
            a[2 * j + 1] += v * f.y;
        }
    }
    *(float4*)&xhat[(size_t)row * ACT + d0] =
        make_float4(a[0], a[1], a[2], a[3]);
    *(float4*)&xhat[(size_t)row * ACT + d0 + 4] =
        make_float4(a[4], a[5], a[6], a[7]);
}

// ---------------- launch ----------------
extern "C" void kernel_launch(void* const* d_in, const int* in_sizes, int n_in,
                              void* d_out, int out_size) {
    (void)in_sizes; (void)n_in; (void)out_size;
    const float* x     = (const float*)d_in[0];
    const float* W_enc = (const float*)d_in[1];
    const float* b_enc = (const float*)d_in[2];
    const float* W_dec = (const float*)d_in[3];
    const float* b_dec = (const float*)d_in[4];
    float* xhat = (float*)d_out;
    float* z    = xhat + (size_t)BATCH * ACT;

    prep_a_kernel<<<(BATCH * (size_t)ACT) / 1024, 256>>>(x, b_dec);
    prep_b_kernel<<<(DICT * (size_t)ACT) / 1024, 256>>>(W_enc);
    transpose_kernel<<<dim3(DICT / 32, ACT / 32), dim3(32, 8)>>>(W_dec);

    cudaFuncSetAttribute(encode_gemm_kernel,
                         cudaFuncAttributeMaxDynamicSharedMemorySize, GEMM_SMEM);
    encode_gemm_kernel<<<dim3(BATCH / BM, DICT / BN), 256, GEMM_SMEM>>>(b_enc, z);

    cudaFuncSetAttribute(topk_kernel,
                         cudaFuncAttributeMaxDynamicSharedMemorySize, DICT * 4);
    topk_kernel<<<BATCH, 512, DICT * 4>>>(x, W_enc, b_enc, b_dec, z);

    decode_kernel<<<BATCH, 256>>>(b_dec, xhat);
}

// round 9
// speedup vs baseline: 2.5848x; 1.1059x over previous
#include <cuda_runtime.h>
#include <cuda_fp16.h>
#include <cstdint>

#define BATCH 4096
#define ACT   2048
#define DICT  32768
#define K_TOP 64
#define EPS   5e-3f
#define CAND_CAP 256

// ---------------- device scratch (static, no allocations) ----------------
__device__ __half g_Af[(size_t)BATCH * ACT];
__device__ __half g_Bf[(size_t)DICT * ACT];
__device__ __half g_WdecTh[(size_t)DICT * ACT];   // [DICT][ACT] fp16
__device__ float  g_vals[BATCH * K_TOP];
__device__ int    g_idxs[BATCH * K_TOP];

// ---------------- prep: fp32 -> fp16 ----------------
__global__ void prep_a_kernel(const float* __restrict__ x,
                              const float* __restrict__ b_dec) {
    size_t i4 = ((size_t)blockIdx.x * blockDim.x + threadIdx.x) * 4;
    float4 v = *(const float4*)&x[i4];
    int c = (int)(i4 & (ACT - 1));
    float4 b = *(const float4*)&b_dec[c];
    __half2* o = (__half2*)&g_Af[i4];
    o[0] = __floats2half2_rn(v.x - b.x, v.y - b.y);
    o[1] = __floats2half2_rn(v.z - b.z, v.w - b.w);
}

__global__ void prep_b_kernel(const float* __restrict__ W) {
    size_t i4 = ((size_t)blockIdx.x * blockDim.x + threadIdx.x) * 4;
    float4 v = *(const float4*)&W[i4];
    __half2* o = (__half2*)&g_Bf[i4];
    o[0] = __floats2half2_rn(v.x, v.y);
    o[1] = __floats2half2_rn(v.z, v.w);
}

// ---------------- transpose W_dec [ACT][DICT] -> g_WdecTh [DICT][ACT] ----
__global__ void transpose_kernel(const float* __restrict__ W) {
    __shared__ float tile[32][33];
    int bx = blockIdx.x * 32;   // dict dim
    int by = blockIdx.y * 32;   // act dim
    int tx = threadIdx.x, ty = threadIdx.y;  // 32 x 8
#pragma unroll
    for (int j = 0; j < 32; j += 8)
        tile[ty + j][tx] = W[(size_t)(by + ty + j) * DICT + bx + tx];
    __syncthreads();
#pragma unroll
    for (int j = 0; j < 32; j += 8)
        g_WdecTh[(size_t)(bx + ty + j) * ACT + by + tx] =
            __float2half(tile[tx][ty + j]);
}

// ---------------- encode GEMM: z = relu((x-b_dec) @ W_enc^T + b_enc) -----
// single fp16 term, fp32 accumulate; 128x128 tile, BK=64,
// 3-stage cp.async pipeline, ONE __syncthreads per k-tile, 2 CTA/SM
#define BM 128
#define BN 128
#define BK 64
#define SSTR 72                       // fp16 elems per smem row (BK + 8 pad)
#define STAGE_ELEMS (128 * SSTR)      // per matrix per stage (9216)
#define NSTAGE 3
#define GEMM_SMEM (NSTAGE * 2 * STAGE_ELEMS * 2)   // 110592 B; x2 CTA = 216KB

__device__ __forceinline__ void cp16(unsigned saddr, const void* g) {
    asm volatile("cp.async.cg.shared.global [%0], [%1], 16;\n" ::"r"(saddr), "l"(g));
}

#define LDSM4(r, a)                                                          \
    asm volatile(                                                            \
        "ldmatrix.sync.aligned.m8n8.x4.shared.b16 {%0,%1,%2,%3}, [%4];"      \
        : "=r"((r)[0]), "=r"((r)[1]), "=r"((r)[2]), "=r"((r)[3])             \
        : "r"(a))

__device__ __forceinline__ void mma_f16(float* c, const uint32_t* a,
                                        const uint32_t* b) {
    asm volatile(
        "mma.sync.aligned.m16n8k16.row.col.f32.f16.f16.f32 "
        "{%0,%1,%2,%3},{%4,%5,%6,%7},{%8,%9},{%0,%1,%2,%3};\n"
        : "+f"(c[0]), "+f"(c[1]), "+f"(c[2]), "+f"(c[3])
        : "r"(a[0]), "r"(a[1]), "r"(a[2]), "r"(a[3]), "r"(b[0]), "r"(b[1]));
}

__global__ void __launch_bounds__(256, 2)
encode_gemm_kernel(const float* __restrict__ b_enc, float* __restrict__ z) {
    extern __shared__ __align__(16) __half sm[];

    const int tid = threadIdx.x;
    const int by = blockIdx.x * BM;   // batch offset (fast grid dim)
    const int bx = blockIdx.y * BN;   // dict offset
    const int warp = tid >> 5, lane = tid & 31;
    const int wm = (warp & 3) * 32;
    const int wn = (warp >> 2) * 64;
    const int g = lane >> 2, tig = lane & 3;

    const unsigned uS = (unsigned)__cvta_generic_to_shared(sm);

    const int aRow = wm + (lane & 15);
    const int aCol = (lane & 16) >> 1;
    const int bRow = wn + (lane & 7) + ((lane & 16) >> 1);
    const int bCol = lane & 8;

    float acc[2][8][4];
#pragma unroll
    for (int mi = 0; mi < 2; mi++)
#pragma unroll
        for (int ni = 0; ni < 8; ni++)
#pragma unroll
            for (int q = 0; q < 4; q++) acc[mi][ni][q] = 0.f;

    const int KT = ACT / BK;   // 32

#define LOAD_STAGE(stage, kt)                                                  \
    {                                                                          \
        const int koff = (kt) * BK;                                            \
        _Pragma("unroll")                                                      \
        for (int r = 0; r < 4; r++) {                                          \
            int id = tid + r * 256;                                            \
            int row = id >> 3;                                                 \
            int ch = (id & 7) * 8;                                             \
            unsigned sa =                                                      \
                (unsigned)(((stage) * 2 * STAGE_ELEMS + row * SSTR + ch) * 2); \
            cp16(uS + sa, &g_Af[(size_t)(by + row) * ACT + koff + ch]);        \
            cp16(uS + sa + STAGE_ELEMS * 2,                                    \
                 &g_Bf[(size_t)(bx + row) * ACT + koff + ch]);                 \
        }                                                                      \
    }

    LOAD_STAGE(0, 0);
    asm volatile("cp.async.commit_group;\n");
    LOAD_STAGE(1, 1);
    asm volatile("cp.async.commit_group;\n");

    int cur = 0, nxt = 2;
    for (int kt = 0; kt < KT; kt++) {
        if (kt + 2 < KT) {
            asm volatile("cp.async.wait_group 1;\n");
        } else {
            asm volatile("cp.async.wait_group 0;\n");
        }
        __syncthreads();

        if (kt + 2 < KT) {
            LOAD_STAGE(nxt, kt + 2);
            asm volatile("cp.async.commit_group;\n");
        }

        const unsigned uA = uS + (unsigned)(cur * 2 * STAGE_ELEMS * 2);
        const unsigned uB = uA + STAGE_ELEMS * 2;
#pragma unroll
        for (int ks = 0; ks < 4; ks++) {
            const int kcol = ks * 16;
            uint32_t af[2][4];
#pragma unroll
            for (int mi = 0; mi < 2; mi++) {
                unsigned ad =
                    uA + (unsigned)(((aRow + mi * 16) * SSTR + kcol + aCol) * 2);
                LDSM4(af[mi], ad);
            }
            uint32_t bf[8][2];
#pragma unroll
            for (int p = 0; p < 4; p++) {
                unsigned bd =
                    uB + (unsigned)(((bRow + p * 16) * SSTR + kcol + bCol) * 2);
                uint32_t r[4];
                LDSM4(r, bd);
                bf[2 * p][0] = r[0];
                bf[2 * p][1] = r[1];
                bf[2 * p + 1][0] = r[2];
                bf[2 * p + 1][1] = r[3];
            }
#pragma unroll
            for (int ni = 0; ni < 8; ni++)
#pragma unroll
                for (int mi = 0; mi < 2; mi++)
                    mma_f16(acc[mi][ni], af[mi], bf[ni]);
        }
        cur = (cur == 2) ? 0 : cur + 1;
        nxt = (nxt == 2) ? 0 : nxt + 1;
    }

    // epilogue: +b_enc, relu, write straight into z region of d_out
#pragma unroll
    for (int mi = 0; mi < 2; mi++) {
        int r = by + wm + mi * 16 + g;
#pragma unroll
        for (int ni = 0; ni < 8; ni++) {
            int c = bx + wn + ni * 8 + tig * 2;
            float be0 = __ldg(&b_enc[c]);
            float be1 = __ldg(&b_enc[c + 1]);
            float v0 = fmaxf(acc[mi][ni][0] + be0, 0.f);
            float v1 = fmaxf(acc[mi][ni][1] + be1, 0.f);
            float v2 = fmaxf(acc[mi][ni][2] + be0, 0.f);
            float v3 = fmaxf(acc[mi][ni][3] + be1, 0.f);
            *(float2*)&z[(size_t)r * DICT + c] = make_float2(v0, v1);
            *(float2*)&z[(size_t)(r + 8) * DICT + c] = make_float2(v2, v3);
        }
    }
}

// ---------------- per-row top-K: radix select + fp64-exact boundary refine
// 1024 threads/block: halves per-pass trip counts, doubles latency hiding
#define TPB 1024
#define NCHUNK (DICT / TPB)    // 32

__global__ void __launch_bounds__(TPB) topk_kernel(
    const float* __restrict__ x, const float* __restrict__ W_enc,
    const float* __restrict__ b_enc, const float* __restrict__ b_dec,
    float* __restrict__ z) {
    extern __shared__ __align__(16) unsigned su[];   // DICT uints (128 KB)
    __shared__ float s_x[ACT];
    __shared__ unsigned s_hist[256];
    __shared__ unsigned s_gsum[8];
    __shared__ unsigned s_prefix;
    __shared__ int s_remaining;
    __shared__ int s_ncand, s_ncert;
    __shared__ int s_cand_idx[CAND_CAP];
    __shared__ double s_cand_val[CAND_CAP];
    __shared__ int s_cntf[NCHUNK * 32];   // j = c*32 + wid (index order)
    __shared__ int s_excl[NCHUNK * 32];
    __shared__ int s_wtot[32], s_wbase[32];

    const unsigned FULL = 0xffffffffu;
    const int row = blockIdx.x;
    const int tid = threadIdx.x;
    const int lane = tid & 31, wid = tid >> 5;   // wid 0..31
    float* zr = z + (size_t)row * DICT;

    for (int i = tid; i < DICT; i += TPB) {
        float v = zr[i];
        su[i] = __float_as_uint(fmaxf(v, 0.f));
    }
    if (tid == 0) { s_prefix = 0u; s_remaining = K_TOP; s_ncand = 0; s_ncert = 0; }
    __syncthreads();

    // 4-round radix select (MSB->LSB bytes)
#pragma unroll
    for (int shift = 24; shift >= 0; shift -= 8) {
        if (tid < 256) s_hist[tid] = 0u;
        __syncthreads();
        unsigned pfx = s_prefix;
        for (int i = tid; i < DICT; i += TPB) {
            unsigned u = su[i];
            bool ok = (shift == 24) ? true
                                    : ((u >> (shift + 8)) == (pfx >> (shift + 8)));
            if (ok) atomicAdd(&s_hist[(u >> shift) & 255u], 1u);
        }
        __syncthreads();
        if (tid < 256) {
            unsigned v = s_hist[tid];
#pragma unroll
            for (int off = 16; off; off >>= 1)
                v += __shfl_down_sync(FULL, v, off);
            if (lane == 0) s_gsum[tid >> 5] = v;
        }
        __syncthreads();
        if (tid == 0) {
            int rem = s_remaining;
            unsigned acc = 0;
            int grp = 7;
            for (; grp > 0; grp--) {
                if (acc + s_gsum[grp] >= (unsigned)rem) break;
                acc += s_gsum[grp];
            }
            int b = grp * 32 + 31;
            for (; b > grp * 32; b--) {
                if (acc + s_hist[b] >= (unsigned)rem) break;
                acc += s_hist[b];
            }
            s_prefix = pfx | ((unsigned)b << shift);
            s_remaining = rem - (int)acc;
        }
        __syncthreads();
    }

    const float Tf = __uint_as_float(s_prefix);
    const float hi = Tf + EPS;
    const float lo = Tf - EPS;

    // Pass A: count certain ins (v > hi), collect boundary candidates
    {
        int local_cert = 0;
        for (int i = tid; i < DICT; i += TPB) {
            float v = __uint_as_float(su[i]);
            if (v > hi) {
                local_cert++;
            } else if (v >= lo) {
                int p = atomicAdd(&s_ncand, 1);
                if (p < CAND_CAP) s_cand_idx[p] = i;
            }
        }
        atomicAdd(&s_ncert, local_cert);
    }
    __syncthreads();

    const int ncand = min(s_ncand, CAND_CAP);
    const int slots = K_TOP - s_ncert;

    if (ncand > 0) {
        for (int k = tid; k < ACT; k += TPB)
            s_x[k] = x[(size_t)row * ACT + k] - b_dec[k];
        __syncthreads();

        // near-exact pre_act: fp64 lane chains + fp64 tree reduce
        for (int c = wid; c < ncand; c += 32) {
            const int m = s_cand_idx[c];
            const float* w = &W_enc[(size_t)m * ACT];
            double acc = 0.0;
            const int k0 = lane * (ACT / 32);
#pragma unroll 8
            for (int k = k0; k < k0 + ACT / 32; k++)
                acc = fma((double)s_x[k], (double)__ldg(&w[k]), acc);
#pragma unroll
            for (int off = 16; off; off >>= 1)
                acc += __shfl_down_sync(FULL, acc, off);
            if (lane == 0) {
                double v = acc + (double)__ldg(&b_enc[m]);
                s_cand_val[c] = v > 0.0 ? v : 0.0;
            }
        }
        __syncthreads();

        if (tid < ncand) {
            const double vi = s_cand_val[tid];
            const int ii = s_cand_idx[tid];
            int r = 0;
            for (int j = 0; j < ncand; j++) {
                double vj = s_cand_val[j];
                if (vj > vi || (vj == vi && s_cand_idx[j] < ii)) r++;
            }
            su[ii] = (r < slots) ? (__float_as_uint((float)vi) | 0x80000000u) : 0u;
        }
        __syncthreads();
    }

    // Pass D1: per-(chunk,warp) selection counts
#pragma unroll 4
    for (int c = 0; c < NCHUNK; c++) {
        int i = c * TPB + tid;
        unsigned u = su[i];
        bool sel = (u & 0x80000000u) || (__uint_as_float(u & 0x7fffffffu) > hi);
        unsigned b = __ballot_sync(FULL, sel);
        if (lane == 0) s_cntf[c * 32 + wid] = __popc(b);
    }
    __syncthreads();

    // scan: warp w handles contiguous j block [32w, 32w+32)
    {
        int j = wid * 32 + lane;
        int a = s_cntf[j];
        int s = a;
#pragma unroll
        for (int off = 1; off < 32; off <<= 1) {
            int t = __shfl_up_sync(FULL, s, off);
            if (lane >= off) s += t;
        }
        s_excl[j] = s - a;
        if (lane == 31) s_wtot[wid] = s;
    }
    __syncthreads();
    if (wid == 0) {
        int v = s_wtot[lane];
        int s = v;
#pragma unroll
        for (int off = 1; off < 32; off <<= 1) {
            int t = __shfl_up_sync(FULL, s, off);
            if (lane >= off) s += t;
        }
        s_wbase[lane] = s - v;
    }
    __syncthreads();

    // Pass D2: write z + compact (idx,val) lists, sync-free
    const unsigned lmask = (1u << lane) - 1u;
#pragma unroll 4
    for (int c = 0; c < NCHUNK; c++) {
        int i = c * TPB + tid;
        unsigned u = su[i];
        bool selc = (u & 0x80000000u) != 0u;
        float uv = __uint_as_float(u & 0x7fffffffu);
        bool sel = selc || (uv > hi);
        unsigned b = __ballot_sync(FULL, sel);
        zr[i] = sel ? uv : 0.f;
        if (sel) {
            int j = c * 32 + wid;
            int slot = s_wbase[j >> 5] + s_excl[j] + __popc(b & lmask);
            g_idxs[row * K_TOP + slot] = i;
            g_vals[row * K_TOP + slot] = uv;
        }
    }
}

// ---------------- decode: x_hat = sum_k vals * W_decTh[idx] + b_dec ------
__global__ void __launch_bounds__(256)
decode_kernel(const float* __restrict__ b_dec, float* __restrict__ xhat) {
    __shared__ int s_idx[K_TOP];
    __shared__ float s_val[K_TOP];
    const int row = blockIdx.x;
    const int tid = threadIdx.x;
    if (tid < K_TOP) {
        s_idx[tid] = g_idxs[row * K_TOP + tid];
        s_val[tid] = g_vals[row * K_TOP + tid];
    }
    __syncthreads();
    const int d0 = tid * 8;
    float a[8];
#pragma unroll
    for (int j = 0; j < 8; j += 4) {
        float4 b4 = *(const float4*)&b_dec[d0 + j];
        a[j] = b4.x; a[j + 1] = b4.y; a[j + 2] = b4.z; a[j + 3] = b4.w;
    }
#pragma unroll 4
    for (int k = 0; k < K_TOP; k++) {
        const __half2* w = (const __half2*)&g_WdecTh[(size_t)s_idx[k] * ACT + d0];
        float v = s_val[k];
#pragma unroll
        for (int j = 0; j < 4; j++) {
            float2 f = __half22float2(w[j]);
            a[2 * j]     += v * f.x;
            a[2 * j + 1] += v * f.y;
        }
    }
    *(float4*)&xhat[(size_t)row * ACT + d0] =
        make_float4(a[0], a[1], a[2], a[3]);
    *(float4*)&xhat[(size_t)row * ACT + d0 + 4] =
        make_float4(a[4], a[5], a[6], a[7]);
}

// ---------------- launch ----------------
extern "C" void kernel_launch(void* const* d_in, const int* in_sizes, int n_in,
                              void* d_out, int out_size) {
    (void)in_sizes; (void)n_in; (void)out_size;
    const float* x     = (const float*)d_in[0];
    const float* W_enc = (const float*)d_in[1];
    const float* b_enc = (const float*)d_in[2];
    const float* W_dec = (const float*)d_in[3];
    const float* b_dec = (const float*)d_in[4];
    float* xhat = (float*)d_out;
    float* z    = xhat + (size_t)BATCH * ACT;

    prep_a_kernel<<<(BATCH * (size_t)ACT) / 1024, 256>>>(x, b_dec);
    prep_b_kernel<<<(DICT * (size_t)ACT) / 1024, 256>>>(W_enc);
    transpose_kernel<<<dim3(DICT / 32, ACT / 32), dim3(32, 8)>>>(W_dec);

    cudaFuncSetAttribute(encode_gemm_kernel,
                         cudaFuncAttributeMaxDynamicSharedMemorySize, GEMM_SMEM);
    encode_gemm_kernel<<<dim3(BATCH / BM, DICT / BN), 256, GEMM_SMEM>>>(b_enc, z);

    cudaFuncSetAttribute(topk_kernel,
                         cudaFuncAttributeMaxDynamicSharedMemorySize, DICT * 4);
    topk_kernel<<<BATCH, TPB, DICT * 4>>>(x, W_enc, b_enc, b_dec, z);

    decode_kernel<<<BATCH, 256>>>(b_dec, xhat);
}